// round 7
// baseline (speedup 1.0000x reference)
#include <cuda_runtime.h>
#include <cuda_bf16.h>
#include <math.h>

// Problem constants
#define T_TOK 3072
#define HID 5120
#define NH 16
#define DN 128
#define DR 64
#define DQK 192       // DN + DR
#define DV 128
#define Q_RANK 1536
#define KV_RANK 512
#define KV_A_OUT (KV_RANK + DR)   // 576
#define KV_OUT (DN + DV)          // 256
#define FUSED_N (Q_RANK + KV_A_OUT)   // 2112

typedef __nv_bfloat16 bf16;

// ---------------------------------------------------------------------------
// Scratch (allocation-free: __device__ globals)
// ---------------------------------------------------------------------------
__device__ bf16 g_Hh[T_TOK * HID],        g_Hl[T_TOK * HID];
__device__ bf16 g_Wa_h[HID * FUSED_N],    g_Wa_l[HID * FUSED_N];   // fused [5120,2112]
__device__ bf16 g_Wqb_h[Q_RANK * NH * DQK],  g_Wqb_l[Q_RANK * NH * DQK];
__device__ bf16 g_Wkvb_h[KV_RANK * NH * KV_OUT], g_Wkvb_l[KV_RANK * NH * KV_OUT];
__device__ bf16 g_Wo_h[NH * DV * HID],    g_Wo_l[NH * DV * HID];
__device__ float g_qalat[T_TOK * FUSED_N];    // fused qa | latent
__device__ bf16  g_qa_h[T_TOK * Q_RANK], g_qa_l[T_TOK * Q_RANK];
__device__ bf16  g_kvan_h[T_TOK * KV_RANK], g_kvan_l[T_TOK * KV_RANK];
__device__ float g_q[T_TOK * NH * DQK];
__device__ float g_kv[T_TOK * NH * KV_OUT];
// head-major split tensors for flash mma
__device__ bf16 g_qh[NH * T_TOK * DQK], g_ql[NH * T_TOK * DQK];
__device__ bf16 g_kh[NH * T_TOK * DQK], g_kl[NH * T_TOK * DQK];
__device__ bf16 g_vh[NH * T_TOK * DV],  g_vl[NH * T_TOK * DV];
__device__ bf16 g_attn_h[T_TOK * NH * DV], g_attn_l[T_TOK * NH * DV];

// ---------------------------------------------------------------------------
// PTX helpers
// ---------------------------------------------------------------------------
__device__ __forceinline__ unsigned smem_u32(const void* p) {
    return (unsigned)__cvta_generic_to_shared(p);
}
__device__ __forceinline__ void cp16(unsigned s, const void* g, int srcsz) {
    asm volatile("cp.async.cg.shared.global [%0], [%1], 16, %2;\n"
                 :: "r"(s), "l"(g), "r"(srcsz));
}
__device__ __forceinline__ void cp_commit() {
    asm volatile("cp.async.commit_group;\n" ::);
}
template<int N> __device__ __forceinline__ void cp_wait() {
    asm volatile("cp.async.wait_group %0;\n" :: "n"(N));
}
__device__ __forceinline__ void ldm4(unsigned* d, unsigned a) {
    asm volatile("ldmatrix.sync.aligned.m8n8.x4.shared.b16 {%0,%1,%2,%3}, [%4];\n"
                 : "=r"(d[0]), "=r"(d[1]), "=r"(d[2]), "=r"(d[3]) : "r"(a));
}
__device__ __forceinline__ void ldm4t(unsigned* d, unsigned a) {
    asm volatile("ldmatrix.sync.aligned.m8n8.x4.trans.shared.b16 {%0,%1,%2,%3}, [%4];\n"
                 : "=r"(d[0]), "=r"(d[1]), "=r"(d[2]), "=r"(d[3]) : "r"(a));
}
__device__ __forceinline__ void mma16816(float* c, const unsigned* a, const unsigned* b) {
    asm volatile(
        "mma.sync.aligned.m16n8k16.row.col.f32.bf16.bf16.f32 "
        "{%0,%1,%2,%3}, {%4,%5,%6,%7}, {%8,%9}, {%0,%1,%2,%3};\n"
        : "+f"(c[0]), "+f"(c[1]), "+f"(c[2]), "+f"(c[3])
        : "r"(a[0]), "r"(a[1]), "r"(a[2]), "r"(a[3]), "r"(b[0]), "r"(b[1]));
}
__device__ __forceinline__ void split1(float x, bf16& h, bf16& l) {
    h = __float2bfloat16_rn(x);
    l = __float2bfloat16_rn(x - __bfloat162float(h));
}
__device__ __forceinline__ unsigned packbf(bf16 a, bf16 b) {
    __nv_bfloat162 t(a, b);
    return *(unsigned*)&t;
}

// ---------------------------------------------------------------------------
// Split-convert: fp32 -> (hi, lo) bf16. n multiple of 4.
// ---------------------------------------------------------------------------
__global__ void split_kernel(const float* __restrict__ x,
                             bf16* __restrict__ hi, bf16* __restrict__ lo, int n4)
{
    int i = blockIdx.x * blockDim.x + threadIdx.x;
    if (i >= n4) return;
    float4 v = ((const float4*)x)[i];
    bf16 h0, h1, h2, h3, l0, l1, l2, l3;
    split1(v.x, h0, l0); split1(v.y, h1, l1); split1(v.z, h2, l2); split1(v.w, h3, l3);
    __nv_bfloat162* H = (__nv_bfloat162*)hi;
    __nv_bfloat162* L = (__nv_bfloat162*)lo;
    H[i * 2]     = __nv_bfloat162(h0, h1);
    H[i * 2 + 1] = __nv_bfloat162(h2, h3);
    L[i * 2]     = __nv_bfloat162(l0, l1);
    L[i * 2 + 1] = __nv_bfloat162(l2, l3);
}

// ---------------------------------------------------------------------------
// Fused-weight split: w_q_a [5120,1536] | w_kv_a [5120,576] -> [5120,2112] hi/lo
// ---------------------------------------------------------------------------
__global__ void split_fuse_kernel(const float* __restrict__ wqa,
                                  const float* __restrict__ wkva,
                                  bf16* __restrict__ hi, bf16* __restrict__ lo)
{
    int i = blockIdx.x * blockDim.x + threadIdx.x;
    int total4 = HID * FUSED_N / 4;
    if (i >= total4) return;
    int e0 = i * 4;
    int k = e0 / FUSED_N, n = e0 % FUSED_N;
    float v[4];
    if (n + 3 < Q_RANK) {
        const float* src = wqa + (size_t)k * Q_RANK + n;
        v[0] = src[0]; v[1] = src[1]; v[2] = src[2]; v[3] = src[3];
    } else if (n >= Q_RANK) {
        const float* src = wkva + (size_t)k * KV_A_OUT + (n - Q_RANK);
        v[0] = src[0]; v[1] = src[1]; v[2] = src[2]; v[3] = src[3];
    } else {
#pragma unroll
        for (int j = 0; j < 4; j++) {
            int nn = n + j;
            v[j] = (nn < Q_RANK) ? wqa[(size_t)k * Q_RANK + nn]
                                 : wkva[(size_t)k * KV_A_OUT + (nn - Q_RANK)];
        }
    }
    bf16 h[4], l[4];
#pragma unroll
    for (int j = 0; j < 4; j++) split1(v[j], h[j], l[j]);
    *(uint2*)(hi + e0) = *(uint2*)h;
    *(uint2*)(lo + e0) = *(uint2*)l;
}

// ---------------------------------------------------------------------------
// Split-bf16 tensor-core GEMM:
// CTA 128x128, BK=64, 256 threads (8 warps, warp tile 64x32), 3-stage
// cp.async pipeline (64KB/stage, 192KB total), XOR-swizzled smem + ldmatrix.
// 3-term split: Ah*Bh + Ah*Bl + Al*Bh, fp32 accumulate.
// Requires: M%128==0, K%64==0, N%8==0.
// ---------------------------------------------------------------------------
#define CBM 128
#define CBN 128
#define CBK 64
#define A_TILE_B 16384     // 128 rows * 128B
#define B_TILE_B 16384     // 64 rows * 256B
#define STAGE_B  (2 * A_TILE_B + 2 * B_TILE_B)   // 65536
#define NSTAGE 3
#define GEMM_SMEM (NSTAGE * STAGE_B)             // 196608

__global__ __launch_bounds__(256) void mma_gemm_kernel(
    const bf16* __restrict__ Ah, const bf16* __restrict__ Al,
    const bf16* __restrict__ Bh, const bf16* __restrict__ Bl,
    float* __restrict__ C, int M, int N, int K)
{
    extern __shared__ char smem[];
    const int tid  = threadIdx.x;
    const int lane = tid & 31;
    const int warp = tid >> 5;
    const int wm0 = (warp >> 2) * 64;
    const int wn0 = (warp & 3) * 32;
    const int m0 = blockIdx.y * CBM;
    const int n0 = blockIdx.x * CBN;

    float acc[16][4];
#pragma unroll
    for (int i = 0; i < 16; i++)
#pragma unroll
        for (int j = 0; j < 4; j++) acc[i][j] = 0.f;

    auto load_stage = [&](int k0, int s) {
        char* base = smem + s * STAGE_B;
        // A: 128 rows x 8 16B-chunks (128B rows) = 1024 per half; 4/thread
#pragma unroll
        for (int i = 0; i < 4; i++) {
            int ch = tid + i * 256;
            int r = ch >> 3, c = ch & 7;
            int pc = c ^ (r & 7);
            size_t goff = (size_t)(m0 + r) * K + k0 + c * 8;
            cp16(smem_u32(base + r * 128 + pc * 16), Ah + goff, 16);
            cp16(smem_u32(base + A_TILE_B + r * 128 + pc * 16), Al + goff, 16);
        }
        // B: 64 rows x 16 16B-chunks (256B rows) = 1024 per half; 4/thread
#pragma unroll
        for (int i = 0; i < 4; i++) {
            int ch = tid + i * 256;
            int r = ch >> 4, c = ch & 15;
            int pc = c ^ (r & 7);
            int gn = n0 + c * 8;
            int sz = (gn < N) ? 16 : 0;
            size_t goff = (size_t)(k0 + r) * N + (gn < N ? gn : 0);
            cp16(smem_u32(base + 2 * A_TILE_B + r * 256 + pc * 16), Bh + goff, sz);
            cp16(smem_u32(base + 2 * A_TILE_B + B_TILE_B + r * 256 + pc * 16), Bl + goff, sz);
        }
    };

    auto compute_stage = [&](int s) {
        char* base = smem + s * STAGE_B;
        unsigned aH = smem_u32(base);
        unsigned aL = aH + A_TILE_B;
        unsigned bH = aH + 2 * A_TILE_B;
        unsigned bL = bH + B_TILE_B;
#pragma unroll
        for (int kk = 0; kk < 4; kk++) {      // 4 k16 steps per 64-K chunk
            unsigned ah[4][4], al[4][4], bh[4][2], bl[4][2];
            const int r_lo = lane & 15;
            const int cch = kk * 2 + (lane >> 4);
#pragma unroll
            for (int mi = 0; mi < 4; mi++) {
                int r = wm0 + mi * 16 + r_lo;
                int pc = cch ^ (r & 7);
                unsigned off = (unsigned)(r * 128 + pc * 16);
                ldm4(ah[mi], aH + off);
                ldm4(al[mi], aL + off);
            }
            {
                int r = kk * 16 + (lane & 15);
#pragma unroll
                for (int ni = 0; ni < 2; ni++) {
                    int cc = ((wn0 + ni * 16) >> 3) + ((lane >> 4) & 1);
                    int pc = cc ^ (r & 7);
                    unsigned off = (unsigned)(r * 256 + pc * 16);
                    unsigned t[4];
                    ldm4t(t, bH + off);
                    bh[ni * 2][0] = t[0]; bh[ni * 2][1] = t[1];
                    bh[ni * 2 + 1][0] = t[2]; bh[ni * 2 + 1][1] = t[3];
                    ldm4t(t, bL + off);
                    bl[ni * 2][0] = t[0]; bl[ni * 2][1] = t[1];
                    bl[ni * 2 + 1][0] = t[2]; bl[ni * 2 + 1][1] = t[3];
                }
            }
#pragma unroll
            for (int mi = 0; mi < 4; mi++)
#pragma unroll
                for (int nj = 0; nj < 4; nj++) {
                    mma16816(acc[mi * 4 + nj], ah[mi], bh[nj]);
                    mma16816(acc[mi * 4 + nj], ah[mi], bl[nj]);
                    mma16816(acc[mi * 4 + nj], al[mi], bh[nj]);
                }
        }
    };

    const int KT = K / CBK;    // HID:80, Q_RANK:24, KV_RANK:8, NH*DV:32
    load_stage(0, 0); cp_commit();
    load_stage(CBK, 1); cp_commit();
    for (int kt = 0; kt < KT; kt++) {
        cp_wait<1>();
        __syncthreads();
        if (kt + 2 < KT) load_stage((kt + 2) * CBK, (kt + 2) % NSTAGE);
        cp_commit();
        compute_stage(kt % NSTAGE);
    }

#pragma unroll
    for (int mi = 0; mi < 4; mi++) {
        int row = m0 + wm0 + mi * 16 + (lane >> 2);
#pragma unroll
        for (int nj = 0; nj < 4; nj++) {
            int col = n0 + wn0 + nj * 8 + (lane & 3) * 2;
            if (col < N) {
                float* a = acc[mi * 4 + nj];
                *(float2*)(C + (size_t)row * N + col)       = make_float2(a[0], a[1]);
                *(float2*)(C + (size_t)(row + 8) * N + col) = make_float2(a[2], a[3]);
            }
        }
    }
}

// ---------------------------------------------------------------------------
// RMSNorm + split (input row stride decoupled from width)
// ---------------------------------------------------------------------------
__global__ void rmsnorm_split_kernel(const float* __restrict__ in,
                                     const float* __restrict__ w,
                                     bf16* __restrict__ ohi, bf16* __restrict__ olo,
                                     int W, int in_stride)
{
    const int t = blockIdx.x;
    const float* row = in + (size_t)t * in_stride;

    float ss = 0.f;
    for (int i = threadIdx.x; i < W; i += blockDim.x) {
        float v = row[i];
        ss += v * v;
    }
    __shared__ float red[32];
#pragma unroll
    for (int o = 16; o; o >>= 1) ss += __shfl_xor_sync(0xffffffffu, ss, o);
    if ((threadIdx.x & 31) == 0) red[threadIdx.x >> 5] = ss;
    __syncthreads();
    if (threadIdx.x < 32) {
        float v = (threadIdx.x < (blockDim.x >> 5)) ? red[threadIdx.x] : 0.f;
#pragma unroll
        for (int o = 16; o; o >>= 1) v += __shfl_xor_sync(0xffffffffu, v, o);
        if (threadIdx.x == 0) red[0] = v;
    }
    __syncthreads();
    const float inv = rsqrtf(red[0] / (float)W + 1e-6f);
    for (int i = threadIdx.x; i < W; i += blockDim.x) {
        float y = row[i] * inv * w[i];
        bf16 h, l;
        split1(y, h, l);
        ohi[(size_t)t * W + i] = h;
        olo[(size_t)t * W + i] = l;
    }
}

// ---------------------------------------------------------------------------
// Prep: RoPE q_pe (in place) + k_pe, fold (scaling * 1/sqrt(192)) into q,
// split q/k/v into head-major (hi, lo) bf16 for flash mma.
// ---------------------------------------------------------------------------
__global__ void prep_kernel(const int* __restrict__ positions,
                            const float* __restrict__ cs_cache,
                            const float* __restrict__ scaling,
                            const float* __restrict__ latent, int lat_stride,
                            float* __restrict__ qb,          // [T,16,192] in/out
                            const float* __restrict__ kvb,   // [T,16,256]
                            bf16* __restrict__ qh, bf16* __restrict__ ql,
                            bf16* __restrict__ kh, bf16* __restrict__ kl,
                            bf16* __restrict__ vh, bf16* __restrict__ vl)
{
    __shared__ float kpe_s[DR];
    const int t = blockIdx.x;
    const int pos = positions[t];
    const float* cs = cs_cache + (size_t)pos * DR;
    const float qsc = scaling[t] * 0.07216878364870322f;  // llama4 * 1/sqrt(192)
    float* qrow = qb + (size_t)t * (NH * DQK);

    for (int idx = threadIdx.x; idx < NH * 32; idx += blockDim.x) {
        int hh = idx >> 5, i = idx & 31;
        float c = cs[i], s = cs[32 + i];
        float x1 = qrow[hh * DQK + DN + i];
        float x2 = qrow[hh * DQK + DN + 32 + i];
        qrow[hh * DQK + DN + i]      = x1 * c - x2 * s;
        qrow[hh * DQK + DN + 32 + i] = x2 * c + x1 * s;
    }
    if (threadIdx.x < 32) {
        int i = threadIdx.x;
        float c = cs[i], s = cs[32 + i];
        float x1 = latent[(size_t)t * lat_stride + KV_RANK + i];
        float x2 = latent[(size_t)t * lat_stride + KV_RANK + 32 + i];
        kpe_s[i]      = x1 * c - x2 * s;
        kpe_s[32 + i] = x2 * c + x1 * s;
    }
    __syncthreads();
    for (int idx = threadIdx.x; idx < NH * DQK; idx += blockDim.x) {
        int hh = idx / DQK, d = idx % DQK;
        size_t o = ((size_t)hh * T_TOK + t) * DQK + d;
        bf16 hi, lo;
        split1(qrow[idx] * qsc, hi, lo);
        qh[o] = hi; ql[o] = lo;
        float kvv = (d < DN) ? kvb[(size_t)t * (NH * KV_OUT) + hh * KV_OUT + d]
                             : kpe_s[d - DN];
        split1(kvv, hi, lo);
        kh[o] = hi; kl[o] = lo;
    }
    for (int idx = threadIdx.x; idx < NH * DV; idx += blockDim.x) {
        int hh = idx / DV, d = idx % DV;
        size_t o = ((size_t)hh * T_TOK + t) * DV + d;
        bf16 hi, lo;
        split1(kvb[(size_t)t * (NH * KV_OUT) + hh * KV_OUT + DN + d], hi, lo);
        vh[o] = hi; vl[o] = lo;
    }
}

// ---------------------------------------------------------------------------
// Tensor-core flash attention (split-bf16, causal).
// Heavy-first block ordering: m-tile index is REVERSED vs blockIdx.x so the
// CTAs with the most key-tiles launch (and get scheduled) first.
// ---------------------------------------------------------------------------
#define AM 128
#define AN 64
#define FQH 0
#define FQL (FQH + AM*384)
#define FKH (FQL + AM*384)
#define FKL (FKH + AN*384)
#define FVH (FKL + AN*384)
#define FVL (FVH + AN*256)
#define FLASH_SMEM (FVL + AN*256)    // 180224 B

__global__ __launch_bounds__(256) void flash_mma_kernel(
    const bf16* __restrict__ qh, const bf16* __restrict__ ql,
    const bf16* __restrict__ kh, const bf16* __restrict__ kl,
    const bf16* __restrict__ vh, const bf16* __restrict__ vl,
    bf16* __restrict__ attn_h, bf16* __restrict__ attn_l)
{
    extern __shared__ char smem[];
    const int mi_idx = gridDim.x - 1 - blockIdx.x;   // heavy-first
    const int m0 = mi_idx * AM;
    const int h  = blockIdx.y;
    const int tid = threadIdx.x, lane = tid & 31, warp = tid >> 5;
    const int wm = warp * 16;
    const float L2E = 1.4426950408889634f;

    {
        const bf16* qh_g = qh + ((size_t)h * T_TOK + m0) * DQK;
        const bf16* ql_g = ql + ((size_t)h * T_TOK + m0) * DQK;
        for (int i = tid; i < AM * 24; i += 256) {
            int r = i / 24, c = i % 24, pc = c ^ (r & 7);
            cp16(smem_u32(smem + FQH + r * 384 + pc * 16), qh_g + (size_t)r * DQK + c * 8, 16);
            cp16(smem_u32(smem + FQL + r * 384 + pc * 16), ql_g + (size_t)r * DQK + c * 8, 16);
        }
        cp_commit();
    }

    float o[16][4];
#pragma unroll
    for (int i = 0; i < 16; i++)
#pragma unroll
        for (int j = 0; j < 4; j++) o[i][j] = 0.f;
    float m0r = -1e30f, m1r = -1e30f, l0 = 0.f, l1 = 0.f;

    const unsigned aQh = smem_u32(smem + FQH), aQl = smem_u32(smem + FQL);
    const unsigned aKh = smem_u32(smem + FKH), aKl = smem_u32(smem + FKL);
    const unsigned aVh = smem_u32(smem + FVH), aVl = smem_u32(smem + FVL);

    const int ntiles = 2 * mi_idx + 2;
    for (int nt = 0; nt < ntiles; nt++) {
        const int n0 = nt * AN;
        __syncthreads();
        {
            const bf16* kh_g = kh + ((size_t)h * T_TOK + n0) * DQK;
            const bf16* kl_g = kl + ((size_t)h * T_TOK + n0) * DQK;
            for (int i = tid; i < AN * 24; i += 256) {
                int r = i / 24, c = i % 24, pc = c ^ (r & 7);
                cp16(smem_u32(smem + FKH + r * 384 + pc * 16), kh_g + (size_t)r * DQK + c * 8, 16);
                cp16(smem_u32(smem + FKL + r * 384 + pc * 16), kl_g + (size_t)r * DQK + c * 8, 16);
            }
            const bf16* vh_g = vh + ((size_t)h * T_TOK + n0) * DV;
            const bf16* vl_g = vl + ((size_t)h * T_TOK + n0) * DV;
            for (int i = tid; i < AN * 16; i += 256) {
                int r = i >> 4, c = i & 15, pc = c ^ (r & 7);
                cp16(smem_u32(smem + FVH + r * 256 + pc * 16), vh_g + (size_t)r * DV + c * 8, 16);
                cp16(smem_u32(smem + FVL + r * 256 + pc * 16), vl_g + (size_t)r * DV + c * 8, 16);
            }
        }
        cp_commit();
        cp_wait<0>();
        __syncthreads();

        float s[8][4];
#pragma unroll
        for (int j = 0; j < 8; j++)
#pragma unroll
            for (int c = 0; c < 4; c++) s[j][c] = 0.f;

#pragma unroll
        for (int kt = 0; kt < 12; kt++) {
            unsigned ah[4], al[4];
            {
                int r = wm + (lane & 15), c = kt * 2 + (lane >> 4);
                int pc = c ^ (r & 7);
                unsigned off = (unsigned)(r * 384 + pc * 16);
                ldm4(ah, aQh + off);
                ldm4(al, aQl + off);
            }
#pragma unroll
            for (int kb = 0; kb < 4; kb++) {
                int r = kb * 16 + (lane & 15), c = kt * 2 + (lane >> 4);
                int pc = c ^ (r & 7);
                unsigned off = (unsigned)(r * 384 + pc * 16);
                unsigned tb[4], tl[4];
                ldm4(tb, aKh + off);
                ldm4(tl, aKl + off);
                unsigned bh0[2] = {tb[0], tb[2]}, bh1[2] = {tb[1], tb[3]};
                unsigned bl0[2] = {tl[0], tl[2]}, bl1[2] = {tl[1], tl[3]};
                mma16816(s[kb * 2], ah, bh0);
                mma16816(s[kb * 2], ah, bl0);
                mma16816(s[kb * 2], al, bh0);
                mma16816(s[kb * 2 + 1], ah, bh1);
                mma16816(s[kb * 2 + 1], ah, bl1);
                mma16816(s[kb * 2 + 1], al, bh1);
            }
        }

        if (n0 + AN > m0) {
            int q0 = m0 + wm + (lane >> 2);
#pragma unroll
            for (int j = 0; j < 8; j++) {
                int k0 = n0 + j * 8 + (lane & 3) * 2;
                if (k0     > q0)     s[j][0] = -1e30f;
                if (k0 + 1 > q0)     s[j][1] = -1e30f;
                if (k0     > q0 + 8) s[j][2] = -1e30f;
                if (k0 + 1 > q0 + 8) s[j][3] = -1e30f;
            }
        }

        float mx0 = -1e30f, mx1 = -1e30f;
#pragma unroll
        for (int j = 0; j < 8; j++) {
            mx0 = fmaxf(mx0, fmaxf(s[j][0], s[j][1]));
            mx1 = fmaxf(mx1, fmaxf(s[j][2], s[j][3]));
        }
        mx0 = fmaxf(mx0, __shfl_xor_sync(0xffffffffu, mx0, 1));
        mx0 = fmaxf(mx0, __shfl_xor_sync(0xffffffffu, mx0, 2));
        mx1 = fmaxf(mx1, __shfl_xor_sync(0xffffffffu, mx1, 1));
        mx1 = fmaxf(mx1, __shfl_xor_sync(0xffffffffu, mx1, 2));
        float mn0 = fmaxf(m0r, mx0), mn1 = fmaxf(m1r, mx1);
        float f0 = exp2f((m0r - mn0) * L2E), f1 = exp2f((m1r - mn1) * L2E);
        m0r = mn0; m1r = mn1;

        unsigned ph[8], ph2[8], pl[8], pl2[8];
        float sum0 = 0.f, sum1 = 0.f;
#pragma unroll
        for (int j = 0; j < 8; j++) {
            float p0 = exp2f((s[j][0] - mn0) * L2E);
            float p1 = exp2f((s[j][1] - mn0) * L2E);
            float p2 = exp2f((s[j][2] - mn1) * L2E);
            float p3 = exp2f((s[j][3] - mn1) * L2E);
            sum0 += p0 + p1; sum1 += p2 + p3;
            bf16 a, b, c, d;
            split1(p0, a, c); split1(p1, b, d);
            ph[j] = packbf(a, b); pl[j] = packbf(c, d);
            split1(p2, a, c); split1(p3, b, d);
            ph2[j] = packbf(a, b); pl2[j] = packbf(c, d);
        }
        sum0 += __shfl_xor_sync(0xffffffffu, sum0, 1);
        sum0 += __shfl_xor_sync(0xffffffffu, sum0, 2);
        sum1 += __shfl_xor_sync(0xffffffffu, sum1, 1);
        sum1 += __shfl_xor_sync(0xffffffffu, sum1, 2);
        l0 = l0 * f0 + sum0;
        l1 = l1 * f1 + sum1;
#pragma unroll
        for (int j = 0; j < 16; j++) {
            o[j][0] *= f0; o[j][1] *= f0; o[j][2] *= f1; o[j][3] *= f1;
        }

#pragma unroll
        for (int kt = 0; kt < 4; kt++) {
            unsigned ahp[4] = {ph[2 * kt], ph2[2 * kt], ph[2 * kt + 1], ph2[2 * kt + 1]};
            unsigned alp[4] = {pl[2 * kt], pl2[2 * kt], pl[2 * kt + 1], pl2[2 * kt + 1]};
#pragma unroll
            for (int nv = 0; nv < 8; nv++) {
                int r = kt * 16 + (lane & 15), c = nv * 2 + (lane >> 4);
                int pc = c ^ (r & 7);
                unsigned off = (unsigned)(r * 256 + pc * 16);
                unsigned tb[4], tl[4];
                ldm4t(tb, aVh + off);
                ldm4t(tl, aVl + off);
                unsigned bh0[2] = {tb[0], tb[1]}, bh1[2] = {tb[2], tb[3]};
                unsigned bl0[2] = {tl[0], tl[1]}, bl1[2] = {tl[2], tl[3]};
                mma16816(o[nv * 2], ahp, bh0);
                mma16816(o[nv * 2], ahp, bl0);
                mma16816(o[nv * 2], alp, bh0);
                mma16816(o[nv * 2 + 1], ahp, bh1);
                mma16816(o[nv * 2 + 1], ahp, bl1);
                mma16816(o[nv * 2 + 1], alp, bh1);
            }
        }
    }

    float il0 = 1.f / l0, il1 = 1.f / l1;
    int r0 = m0 + wm + (lane >> 2);
#pragma unroll
    for (int j = 0; j < 16; j++) {
        int dv = j * 8 + (lane & 3) * 2;
        bf16 a, b, c, d;
        split1(o[j][0] * il0, a, c);
        split1(o[j][1] * il0, b, d);
        size_t off = (size_t)r0 * (NH * DV) + h * DV + dv;
        *(__nv_bfloat162*)(attn_h + off) = __nv_bfloat162(a, b);
        *(__nv_bfloat162*)(attn_l + off) = __nv_bfloat162(c, d);
        split1(o[j][2] * il1, a, c);
        split1(o[j][3] * il1, b, d);
        off += (size_t)8 * (NH * DV);
        *(__nv_bfloat162*)(attn_h + off) = __nv_bfloat162(a, b);
        *(__nv_bfloat162*)(attn_l + off) = __nv_bfloat162(c, d);
    }
}

// ---------------------------------------------------------------------------
// Launch
// ---------------------------------------------------------------------------
static inline void launch_split(const float* x, bf16* hi, bf16* lo, int n) {
    int n4 = n / 4;
    split_kernel<<<(n4 + 255) / 256, 256>>>(x, hi, lo, n4);
}

extern "C" void kernel_launch(void* const* d_in, const int* in_sizes, int n_in,
                              void* d_out, int out_size)
{
    const int*   positions = (const int*)  d_in[0];
    const float* hidden    = (const float*)d_in[1];
    const float* scaling   = (const float*)d_in[2];
    const float* w_q_a     = (const float*)d_in[3];
    const float* q_a_ln_w  = (const float*)d_in[4];
    const float* w_q_b     = (const float*)d_in[5];
    const float* w_kv_a    = (const float*)d_in[6];
    const float* kv_a_ln_w = (const float*)d_in[7];
    const float* w_kv_b    = (const float*)d_in[8];
    const float* w_o       = (const float*)d_in[9];
    const float* cs_cache  = (const float*)d_in[10];
    float* out = (float*)d_out;

    bf16 *Hh, *Hl, *Wa_h, *Wa_l, *Wqb_h, *Wqb_l;
    bf16 *Wkvb_h, *Wkvb_l, *Wo_h, *Wo_l, *qa_h, *qa_l, *kvan_h, *kvan_l;
    bf16 *qhp, *qlp, *khp, *klp, *vhp, *vlp, *attn_h, *attn_l;
    float *qalat, *qb, *kv;
    cudaGetSymbolAddress((void**)&Hh, g_Hh);       cudaGetSymbolAddress((void**)&Hl, g_Hl);
    cudaGetSymbolAddress((void**)&Wa_h, g_Wa_h);   cudaGetSymbolAddress((void**)&Wa_l, g_Wa_l);
    cudaGetSymbolAddress((void**)&Wqb_h, g_Wqb_h); cudaGetSymbolAddress((void**)&Wqb_l, g_Wqb_l);
    cudaGetSymbolAddress((void**)&Wkvb_h, g_Wkvb_h); cudaGetSymbolAddress((void**)&Wkvb_l, g_Wkvb_l);
    cudaGetSymbolAddress((void**)&Wo_h, g_Wo_h);   cudaGetSymbolAddress((void**)&Wo_l, g_Wo_l);
    cudaGetSymbolAddress((void**)&qa_h, g_qa_h);   cudaGetSymbolAddress((void**)&qa_l, g_qa_l);
    cudaGetSymbolAddress((void**)&kvan_h, g_kvan_h); cudaGetSymbolAddress((void**)&kvan_l, g_kvan_l);
    cudaGetSymbolAddress((void**)&qhp, g_qh); cudaGetSymbolAddress((void**)&qlp, g_ql);
    cudaGetSymbolAddress((void**)&khp, g_kh); cudaGetSymbolAddress((void**)&klp, g_kl);
    cudaGetSymbolAddress((void**)&vhp, g_vh); cudaGetSymbolAddress((void**)&vlp, g_vl);
    cudaGetSymbolAddress((void**)&attn_h, g_attn_h); cudaGetSymbolAddress((void**)&attn_l, g_attn_l);
    cudaGetSymbolAddress((void**)&qalat, g_qalat);
    cudaGetSymbolAddress((void**)&qb, g_q);
    cudaGetSymbolAddress((void**)&kv, g_kv);

    cudaFuncSetAttribute(mma_gemm_kernel, cudaFuncAttributeMaxDynamicSharedMemorySize,
                         GEMM_SMEM);
    cudaFuncSetAttribute(flash_mma_kernel, cudaFuncAttributeMaxDynamicSharedMemorySize,
                         FLASH_SMEM);

    // 1. split inputs + weights (w_q_a | w_kv_a fused into one [5120,2112])
    launch_split(hidden, Hh, Hl, T_TOK * HID);
    {
        int total4 = HID * FUSED_N / 4;
        split_fuse_kernel<<<(total4 + 255) / 256, 256>>>(w_q_a, w_kv_a, Wa_h, Wa_l);
    }
    launch_split(w_q_b, Wqb_h, Wqb_l, Q_RANK * NH * DQK);
    launch_split(w_kv_b, Wkvb_h, Wkvb_l, KV_RANK * NH * KV_OUT);
    launch_split(w_o, Wo_h, Wo_l, NH * DV * HID);

    const dim3 blk(256);
    const int MT = T_TOK / CBM;  // 24

    // 2. [qa | latent] = hidden @ [w_q_a | w_kv_a]   [3072,5120]x[5120,2112]
    mma_gemm_kernel<<<dim3((FUSED_N + CBN - 1) / CBN, MT), blk, GEMM_SMEM>>>(
        Hh, Hl, Wa_h, Wa_l, qalat, T_TOK, FUSED_N, HID);
    // 3. rmsnorm + split (qa: cols 0-1535; kv_a: cols 1536-2047 of fused rows)
    rmsnorm_split_kernel<<<T_TOK, 256>>>(qalat, q_a_ln_w, qa_h, qa_l, Q_RANK, FUSED_N);
    rmsnorm_split_kernel<<<T_TOK, 256>>>(qalat + Q_RANK, kv_a_ln_w, kvan_h, kvan_l,
                                         KV_RANK, FUSED_N);
    // 4. q = qa_n @ w_q_b   [3072,1536]x[1536,3072]
    mma_gemm_kernel<<<dim3((NH * DQK) / CBN, MT), blk, GEMM_SMEM>>>(
        qa_h, qa_l, Wqb_h, Wqb_l, qb, T_TOK, NH * DQK, Q_RANK);
    // 5. kv = kvan @ w_kv_b   [3072,512]x[512,4096]
    mma_gemm_kernel<<<dim3((NH * KV_OUT) / CBN, MT), blk, GEMM_SMEM>>>(
        kvan_h, kvan_l, Wkvb_h, Wkvb_l, kv, T_TOK, NH * KV_OUT, KV_RANK);
    // 6. rope + scale folding + head-major splits (latent = fused cols 1536+)
    prep_kernel<<<T_TOK, 256>>>(positions, cs_cache, scaling,
                                qalat + Q_RANK, FUSED_N, qb, kv,
                                qhp, qlp, khp, klp, vhp, vlp);
    // 7. tensor-core flash attention (heavy-first ordering)
    flash_mma_kernel<<<dim3(T_TOK / AM, NH), 256, FLASH_SMEM>>>(
        qhp, qlp, khp, klp, vhp, vlp, attn_h, attn_l);
    // 8. out = attn @ w_o   [3072,2048]x[2048,5120]
    mma_gemm_kernel<<<dim3(HID / CBN, MT), blk, GEMM_SMEM>>>(
        attn_h, attn_l, Wo_h, Wo_l, out, T_TOK, HID, NH * DV);
}

// round 8
// speedup vs baseline: 1.0009x; 1.0009x over previous
#include <cuda_runtime.h>
#include <cuda_bf16.h>
#include <math.h>

// Problem constants
#define T_TOK 3072
#define HID 5120
#define NH 16
#define DN 128
#define DR 64
#define DQK 192       // DN + DR
#define DV 128
#define Q_RANK 1536
#define KV_RANK 512
#define KV_A_OUT (KV_RANK + DR)   // 576
#define KV_OUT (DN + DV)          // 256
#define FUSED_N (Q_RANK + KV_A_OUT)   // 2112

typedef __nv_bfloat16 bf16;

// ---------------------------------------------------------------------------
// Scratch (allocation-free: __device__ globals)
// ---------------------------------------------------------------------------
__device__ bf16 g_Hh[T_TOK * HID],        g_Hl[T_TOK * HID];
__device__ bf16 g_Wa_h[HID * FUSED_N],    g_Wa_l[HID * FUSED_N];   // fused [5120,2112]
__device__ bf16 g_Wqb_h[Q_RANK * NH * DQK],  g_Wqb_l[Q_RANK * NH * DQK];
__device__ bf16 g_Wkvb_h[KV_RANK * NH * KV_OUT], g_Wkvb_l[KV_RANK * NH * KV_OUT];
__device__ bf16 g_Wo_h[NH * DV * HID],    g_Wo_l[NH * DV * HID];
__device__ float g_qalat[T_TOK * FUSED_N];    // fused qa | latent
__device__ bf16  g_qa_h[T_TOK * Q_RANK], g_qa_l[T_TOK * Q_RANK];
__device__ bf16  g_kvan_h[T_TOK * KV_RANK], g_kvan_l[T_TOK * KV_RANK];
__device__ float g_q[T_TOK * NH * DQK];
__device__ float g_kv[T_TOK * NH * KV_OUT];
// head-major split tensors for flash mma
__device__ bf16 g_qh[NH * T_TOK * DQK], g_ql[NH * T_TOK * DQK];
__device__ bf16 g_kh[NH * T_TOK * DQK], g_kl[NH * T_TOK * DQK];
__device__ bf16 g_vh[NH * T_TOK * DV],  g_vl[NH * T_TOK * DV];
__device__ bf16 g_attn_h[T_TOK * NH * DV], g_attn_l[T_TOK * NH * DV];

// ---------------------------------------------------------------------------
// PTX helpers
// ---------------------------------------------------------------------------
__device__ __forceinline__ unsigned smem_u32(const void* p) {
    return (unsigned)__cvta_generic_to_shared(p);
}
__device__ __forceinline__ void cp16(unsigned s, const void* g, int srcsz) {
    asm volatile("cp.async.cg.shared.global [%0], [%1], 16, %2;\n"
                 :: "r"(s), "l"(g), "r"(srcsz));
}
__device__ __forceinline__ void cp_commit() {
    asm volatile("cp.async.commit_group;\n" ::);
}
template<int N> __device__ __forceinline__ void cp_wait() {
    asm volatile("cp.async.wait_group %0;\n" :: "n"(N));
}
__device__ __forceinline__ void ldm4(unsigned* d, unsigned a) {
    asm volatile("ldmatrix.sync.aligned.m8n8.x4.shared.b16 {%0,%1,%2,%3}, [%4];\n"
                 : "=r"(d[0]), "=r"(d[1]), "=r"(d[2]), "=r"(d[3]) : "r"(a));
}
__device__ __forceinline__ void ldm4t(unsigned* d, unsigned a) {
    asm volatile("ldmatrix.sync.aligned.m8n8.x4.trans.shared.b16 {%0,%1,%2,%3}, [%4];\n"
                 : "=r"(d[0]), "=r"(d[1]), "=r"(d[2]), "=r"(d[3]) : "r"(a));
}
__device__ __forceinline__ void mma16816(float* c, const unsigned* a, const unsigned* b) {
    asm volatile(
        "mma.sync.aligned.m16n8k16.row.col.f32.bf16.bf16.f32 "
        "{%0,%1,%2,%3}, {%4,%5,%6,%7}, {%8,%9}, {%0,%1,%2,%3};\n"
        : "+f"(c[0]), "+f"(c[1]), "+f"(c[2]), "+f"(c[3])
        : "r"(a[0]), "r"(a[1]), "r"(a[2]), "r"(a[3]), "r"(b[0]), "r"(b[1]));
}
__device__ __forceinline__ void split1(float x, bf16& h, bf16& l) {
    h = __float2bfloat16_rn(x);
    l = __float2bfloat16_rn(x - __bfloat162float(h));
}
__device__ __forceinline__ unsigned packbf(bf16 a, bf16 b) {
    __nv_bfloat162 t(a, b);
    return *(unsigned*)&t;
}

// ---------------------------------------------------------------------------
// Split-convert: fp32 -> (hi, lo) bf16. n multiple of 4.
// ---------------------------------------------------------------------------
__global__ void split_kernel(const float* __restrict__ x,
                             bf16* __restrict__ hi, bf16* __restrict__ lo, int n4)
{
    int i = blockIdx.x * blockDim.x + threadIdx.x;
    if (i >= n4) return;
    float4 v = ((const float4*)x)[i];
    bf16 h0, h1, h2, h3, l0, l1, l2, l3;
    split1(v.x, h0, l0); split1(v.y, h1, l1); split1(v.z, h2, l2); split1(v.w, h3, l3);
    __nv_bfloat162* H = (__nv_bfloat162*)hi;
    __nv_bfloat162* L = (__nv_bfloat162*)lo;
    H[i * 2]     = __nv_bfloat162(h0, h1);
    H[i * 2 + 1] = __nv_bfloat162(h2, h3);
    L[i * 2]     = __nv_bfloat162(l0, l1);
    L[i * 2 + 1] = __nv_bfloat162(l2, l3);
}

// ---------------------------------------------------------------------------
// Fused-weight split: w_q_a [5120,1536] | w_kv_a [5120,576] -> [5120,2112] hi/lo
// ---------------------------------------------------------------------------
__global__ void split_fuse_kernel(const float* __restrict__ wqa,
                                  const float* __restrict__ wkva,
                                  bf16* __restrict__ hi, bf16* __restrict__ lo)
{
    int i = blockIdx.x * blockDim.x + threadIdx.x;
    int total4 = HID * FUSED_N / 4;
    if (i >= total4) return;
    int e0 = i * 4;
    int k = e0 / FUSED_N, n = e0 % FUSED_N;
    float v[4];
    if (n + 3 < Q_RANK) {
        const float* src = wqa + (size_t)k * Q_RANK + n;
        v[0] = src[0]; v[1] = src[1]; v[2] = src[2]; v[3] = src[3];
    } else if (n >= Q_RANK) {
        const float* src = wkva + (size_t)k * KV_A_OUT + (n - Q_RANK);
        v[0] = src[0]; v[1] = src[1]; v[2] = src[2]; v[3] = src[3];
    } else {
#pragma unroll
        for (int j = 0; j < 4; j++) {
            int nn = n + j;
            v[j] = (nn < Q_RANK) ? wqa[(size_t)k * Q_RANK + nn]
                                 : wkva[(size_t)k * KV_A_OUT + (nn - Q_RANK)];
        }
    }
    bf16 h[4], l[4];
#pragma unroll
    for (int j = 0; j < 4; j++) split1(v[j], h[j], l[j]);
    *(uint2*)(hi + e0) = *(uint2*)h;
    *(uint2*)(lo + e0) = *(uint2*)l;
}

// ---------------------------------------------------------------------------
// Split-bf16 tensor-core GEMM core (R6-proven config):
// CTA 128x128, BK=32, 256 threads (8 warps, warp tile 64x32), 3-stage
// cp.async pipeline (48KB/stage, 96KB total -> 2 CTA/SM), XOR-swizzled smem.
// 3-term split: Ah*Bh + Ah*Bl + Al*Bh, fp32 accumulate.
// ---------------------------------------------------------------------------
#define CBM 128
#define CBN 128
#define CBK 32
#define A_TILE_B 8192
#define B_TILE_B 8192
#define STAGE_B  (2 * A_TILE_B + 2 * B_TILE_B)
#define NSTAGE 3
#define GEMM_SMEM (NSTAGE * STAGE_B)   // 98304

__device__ __forceinline__ void gemm_cta(
    char* smem, int tid,
    const bf16* __restrict__ Ah, const bf16* __restrict__ Al,
    const bf16* __restrict__ Bh, const bf16* __restrict__ Bl,
    float* __restrict__ C, int m0, int n0, int N, int K)
{
    const int lane = tid & 31;
    const int warp = tid >> 5;
    const int wm0 = (warp >> 2) * 64;
    const int wn0 = (warp & 3) * 32;

    float acc[16][4];
#pragma unroll
    for (int i = 0; i < 16; i++)
#pragma unroll
        for (int j = 0; j < 4; j++) acc[i][j] = 0.f;

    auto load_stage = [&](int k0, int s) {
        char* base = smem + s * STAGE_B;
#pragma unroll
        for (int i = 0; i < 2; i++) {
            int ch = tid + i * 256;
            int r = ch >> 2, c = ch & 3;
            int pc = c ^ ((r >> 1) & 3);
            size_t goff = (size_t)(m0 + r) * K + k0 + c * 8;
            cp16(smem_u32(base + r * 64 + pc * 16), Ah + goff, 16);
            cp16(smem_u32(base + A_TILE_B + r * 64 + pc * 16), Al + goff, 16);
        }
#pragma unroll
        for (int i = 0; i < 2; i++) {
            int ch = tid + i * 256;
            int r = ch >> 4, c = ch & 15;
            int pc = c ^ (r & 7);
            int gn = n0 + c * 8;
            int sz = (gn < N) ? 16 : 0;
            size_t goff = (size_t)(k0 + r) * N + (gn < N ? gn : 0);
            cp16(smem_u32(base + 2 * A_TILE_B + r * 256 + pc * 16), Bh + goff, sz);
            cp16(smem_u32(base + 2 * A_TILE_B + B_TILE_B + r * 256 + pc * 16), Bl + goff, sz);
        }
    };

    auto compute_stage = [&](int s) {
        char* base = smem + s * STAGE_B;
        unsigned aH = smem_u32(base);
        unsigned aL = aH + A_TILE_B;
        unsigned bH = aH + 2 * A_TILE_B;
        unsigned bL = bH + B_TILE_B;
#pragma unroll
        for (int kk = 0; kk < 2; kk++) {
            unsigned ah[4][4], al[4][4], bh[4][2], bl[4][2];
            const int r_lo = lane & 15;
            const int cch = kk * 2 + (lane >> 4);
#pragma unroll
            for (int mi = 0; mi < 4; mi++) {
                int r = wm0 + mi * 16 + r_lo;
                int pc = cch ^ ((r >> 1) & 3);
                unsigned off = (unsigned)(r * 64 + pc * 16);
                ldm4(ah[mi], aH + off);
                ldm4(al[mi], aL + off);
            }
            {
                int r = kk * 16 + (lane & 15);
#pragma unroll
                for (int ni = 0; ni < 2; ni++) {
                    int cc = ((wn0 + ni * 16) >> 3) + ((lane >> 4) & 1);
                    int pc = cc ^ (r & 7);
                    unsigned off = (unsigned)(r * 256 + pc * 16);
                    unsigned t[4];
                    ldm4t(t, bH + off);
                    bh[ni * 2][0] = t[0]; bh[ni * 2][1] = t[1];
                    bh[ni * 2 + 1][0] = t[2]; bh[ni * 2 + 1][1] = t[3];
                    ldm4t(t, bL + off);
                    bl[ni * 2][0] = t[0]; bl[ni * 2][1] = t[1];
                    bl[ni * 2 + 1][0] = t[2]; bl[ni * 2 + 1][1] = t[3];
                }
            }
#pragma unroll
            for (int mi = 0; mi < 4; mi++)
#pragma unroll
                for (int nj = 0; nj < 4; nj++) {
                    mma16816(acc[mi * 4 + nj], ah[mi], bh[nj]);
                    mma16816(acc[mi * 4 + nj], ah[mi], bl[nj]);
                    mma16816(acc[mi * 4 + nj], al[mi], bh[nj]);
                }
        }
    };

    const int KT = K / CBK;
    load_stage(0, 0); cp_commit();
    load_stage(CBK, 1); cp_commit();
    for (int kt = 0; kt < KT; kt++) {
        cp_wait<1>();
        __syncthreads();
        if (kt + 2 < KT) load_stage((kt + 2) * CBK, (kt + 2) % NSTAGE);
        cp_commit();
        compute_stage(kt % NSTAGE);
    }

#pragma unroll
    for (int mi = 0; mi < 4; mi++) {
        int row = m0 + wm0 + mi * 16 + (lane >> 2);
#pragma unroll
        for (int nj = 0; nj < 4; nj++) {
            int col = n0 + wn0 + nj * 8 + (lane & 3) * 2;
            if (col < N) {
                float* a = acc[mi * 4 + nj];
                *(float2*)(C + (size_t)row * N + col)       = make_float2(a[0], a[1]);
                *(float2*)(C + (size_t)(row + 8) * N + col) = make_float2(a[2], a[3]);
            }
        }
    }
}

__global__ __launch_bounds__(256) void mma_gemm_kernel(
    const bf16* __restrict__ Ah, const bf16* __restrict__ Al,
    const bf16* __restrict__ Bh, const bf16* __restrict__ Bl,
    float* __restrict__ C, int M, int N, int K)
{
    extern __shared__ char smem[];
    gemm_cta(smem, threadIdx.x, Ah, Al, Bh, Bl, C,
             blockIdx.y * CBM, blockIdx.x * CBN, N, K);
}

// Dual GEMM: first nblk1 n-tiles run problem 1, rest run problem 2.
__global__ __launch_bounds__(256) void mma_gemm_dual_kernel(
    const bf16* __restrict__ Ah1, const bf16* __restrict__ Al1,
    const bf16* __restrict__ Bh1, const bf16* __restrict__ Bl1,
    float* __restrict__ C1, int N1, int K1, int nblk1,
    const bf16* __restrict__ Ah2, const bf16* __restrict__ Al2,
    const bf16* __restrict__ Bh2, const bf16* __restrict__ Bl2,
    float* __restrict__ C2, int N2, int K2)
{
    extern __shared__ char smem[];
    const int m0 = blockIdx.y * CBM;
    if ((int)blockIdx.x < nblk1) {
        gemm_cta(smem, threadIdx.x, Ah1, Al1, Bh1, Bl1, C1,
                 m0, blockIdx.x * CBN, N1, K1);
    } else {
        gemm_cta(smem, threadIdx.x, Ah2, Al2, Bh2, Bl2, C2,
                 m0, (blockIdx.x - nblk1) * CBN, N2, K2);
    }
}

// ---------------------------------------------------------------------------
// RMSNorm + split (input row stride decoupled from width)
// ---------------------------------------------------------------------------
__global__ void rmsnorm_split_kernel(const float* __restrict__ in,
                                     const float* __restrict__ w,
                                     bf16* __restrict__ ohi, bf16* __restrict__ olo,
                                     int W, int in_stride)
{
    const int t = blockIdx.x;
    const float* row = in + (size_t)t * in_stride;

    float ss = 0.f;
    for (int i = threadIdx.x; i < W; i += blockDim.x) {
        float v = row[i];
        ss += v * v;
    }
    __shared__ float red[32];
#pragma unroll
    for (int o = 16; o; o >>= 1) ss += __shfl_xor_sync(0xffffffffu, ss, o);
    if ((threadIdx.x & 31) == 0) red[threadIdx.x >> 5] = ss;
    __syncthreads();
    if (threadIdx.x < 32) {
        float v = (threadIdx.x < (blockDim.x >> 5)) ? red[threadIdx.x] : 0.f;
#pragma unroll
        for (int o = 16; o; o >>= 1) v += __shfl_xor_sync(0xffffffffu, v, o);
        if (threadIdx.x == 0) red[0] = v;
    }
    __syncthreads();
    const float inv = rsqrtf(red[0] / (float)W + 1e-6f);
    for (int i = threadIdx.x; i < W; i += blockDim.x) {
        float y = row[i] * inv * w[i];
        bf16 h, l;
        split1(y, h, l);
        ohi[(size_t)t * W + i] = h;
        olo[(size_t)t * W + i] = l;
    }
}

// ---------------------------------------------------------------------------
// Prep: RoPE q_pe (in place) + k_pe, fold (scaling * 1/sqrt(192)) into q,
// split q/k/v into head-major (hi, lo) bf16 for flash mma.
// ---------------------------------------------------------------------------
__global__ void prep_kernel(const int* __restrict__ positions,
                            const float* __restrict__ cs_cache,
                            const float* __restrict__ scaling,
                            const float* __restrict__ latent, int lat_stride,
                            float* __restrict__ qb,          // [T,16,192] in/out
                            const float* __restrict__ kvb,   // [T,16,256]
                            bf16* __restrict__ qh, bf16* __restrict__ ql,
                            bf16* __restrict__ kh, bf16* __restrict__ kl,
                            bf16* __restrict__ vh, bf16* __restrict__ vl)
{
    __shared__ float kpe_s[DR];
    const int t = blockIdx.x;
    const int pos = positions[t];
    const float* cs = cs_cache + (size_t)pos * DR;
    const float qsc = scaling[t] * 0.07216878364870322f;  // llama4 * 1/sqrt(192)
    float* qrow = qb + (size_t)t * (NH * DQK);

    for (int idx = threadIdx.x; idx < NH * 32; idx += blockDim.x) {
        int hh = idx >> 5, i = idx & 31;
        float c = cs[i], s = cs[32 + i];
        float x1 = qrow[hh * DQK + DN + i];
        float x2 = qrow[hh * DQK + DN + 32 + i];
        qrow[hh * DQK + DN + i]      = x1 * c - x2 * s;
        qrow[hh * DQK + DN + 32 + i] = x2 * c + x1 * s;
    }
    if (threadIdx.x < 32) {
        int i = threadIdx.x;
        float c = cs[i], s = cs[32 + i];
        float x1 = latent[(size_t)t * lat_stride + KV_RANK + i];
        float x2 = latent[(size_t)t * lat_stride + KV_RANK + 32 + i];
        kpe_s[i]      = x1 * c - x2 * s;
        kpe_s[32 + i] = x2 * c + x1 * s;
    }
    __syncthreads();
    for (int idx = threadIdx.x; idx < NH * DQK; idx += blockDim.x) {
        int hh = idx / DQK, d = idx % DQK;
        size_t o = ((size_t)hh * T_TOK + t) * DQK + d;
        bf16 hi, lo;
        split1(qrow[idx] * qsc, hi, lo);
        qh[o] = hi; ql[o] = lo;
        float kvv = (d < DN) ? kvb[(size_t)t * (NH * KV_OUT) + hh * KV_OUT + d]
                             : kpe_s[d - DN];
        split1(kvv, hi, lo);
        kh[o] = hi; kl[o] = lo;
    }
    for (int idx = threadIdx.x; idx < NH * DV; idx += blockDim.x) {
        int hh = idx / DV, d = idx % DV;
        size_t o = ((size_t)hh * T_TOK + t) * DV + d;
        bf16 hi, lo;
        split1(kvb[(size_t)t * (NH * KV_OUT) + hh * KV_OUT + DN + d], hi, lo);
        vh[o] = hi; vl[o] = lo;
    }
}

// ---------------------------------------------------------------------------
// Tensor-core flash attention (split-bf16, causal). Heavy-first ordering.
// ---------------------------------------------------------------------------
#define AM 128
#define AN 64
#define FQH 0
#define FQL (FQH + AM*384)
#define FKH (FQL + AM*384)
#define FKL (FKH + AN*384)
#define FVH (FKL + AN*384)
#define FVL (FVH + AN*256)
#define FLASH_SMEM (FVL + AN*256)    // 180224 B

__global__ __launch_bounds__(256) void flash_mma_kernel(
    const bf16* __restrict__ qh, const bf16* __restrict__ ql,
    const bf16* __restrict__ kh, const bf16* __restrict__ kl,
    const bf16* __restrict__ vh, const bf16* __restrict__ vl,
    bf16* __restrict__ attn_h, bf16* __restrict__ attn_l)
{
    extern __shared__ char smem[];
    const int mi_idx = gridDim.x - 1 - blockIdx.x;   // heavy-first
    const int m0 = mi_idx * AM;
    const int h  = blockIdx.y;
    const int tid = threadIdx.x, lane = tid & 31, warp = tid >> 5;
    const int wm = warp * 16;
    const float L2E = 1.4426950408889634f;

    {
        const bf16* qh_g = qh + ((size_t)h * T_TOK + m0) * DQK;
        const bf16* ql_g = ql + ((size_t)h * T_TOK + m0) * DQK;
        for (int i = tid; i < AM * 24; i += 256) {
            int r = i / 24, c = i % 24, pc = c ^ (r & 7);
            cp16(smem_u32(smem + FQH + r * 384 + pc * 16), qh_g + (size_t)r * DQK + c * 8, 16);
            cp16(smem_u32(smem + FQL + r * 384 + pc * 16), ql_g + (size_t)r * DQK + c * 8, 16);
        }
        cp_commit();
    }

    float o[16][4];
#pragma unroll
    for (int i = 0; i < 16; i++)
#pragma unroll
        for (int j = 0; j < 4; j++) o[i][j] = 0.f;
    float m0r = -1e30f, m1r = -1e30f, l0 = 0.f, l1 = 0.f;

    const unsigned aQh = smem_u32(smem + FQH), aQl = smem_u32(smem + FQL);
    const unsigned aKh = smem_u32(smem + FKH), aKl = smem_u32(smem + FKL);
    const unsigned aVh = smem_u32(smem + FVH), aVl = smem_u32(smem + FVL);

    const int ntiles = 2 * mi_idx + 2;
    for (int nt = 0; nt < ntiles; nt++) {
        const int n0 = nt * AN;
        __syncthreads();
        {
            const bf16* kh_g = kh + ((size_t)h * T_TOK + n0) * DQK;
            const bf16* kl_g = kl + ((size_t)h * T_TOK + n0) * DQK;
            for (int i = tid; i < AN * 24; i += 256) {
                int r = i / 24, c = i % 24, pc = c ^ (r & 7);
                cp16(smem_u32(smem + FKH + r * 384 + pc * 16), kh_g + (size_t)r * DQK + c * 8, 16);
                cp16(smem_u32(smem + FKL + r * 384 + pc * 16), kl_g + (size_t)r * DQK + c * 8, 16);
            }
            const bf16* vh_g = vh + ((size_t)h * T_TOK + n0) * DV;
            const bf16* vl_g = vl + ((size_t)h * T_TOK + n0) * DV;
            for (int i = tid; i < AN * 16; i += 256) {
                int r = i >> 4, c = i & 15, pc = c ^ (r & 7);
                cp16(smem_u32(smem + FVH + r * 256 + pc * 16), vh_g + (size_t)r * DV + c * 8, 16);
                cp16(smem_u32(smem + FVL + r * 256 + pc * 16), vl_g + (size_t)r * DV + c * 8, 16);
            }
        }
        cp_commit();
        cp_wait<0>();
        __syncthreads();

        float s[8][4];
#pragma unroll
        for (int j = 0; j < 8; j++)
#pragma unroll
            for (int c = 0; c < 4; c++) s[j][c] = 0.f;

#pragma unroll
        for (int kt = 0; kt < 12; kt++) {
            unsigned ah[4], al[4];
            {
                int r = wm + (lane & 15), c = kt * 2 + (lane >> 4);
                int pc = c ^ (r & 7);
                unsigned off = (unsigned)(r * 384 + pc * 16);
                ldm4(ah, aQh + off);
                ldm4(al, aQl + off);
            }
#pragma unroll
            for (int kb = 0; kb < 4; kb++) {
                int r = kb * 16 + (lane & 15), c = kt * 2 + (lane >> 4);
                int pc = c ^ (r & 7);
                unsigned off = (unsigned)(r * 384 + pc * 16);
                unsigned tb[4], tl[4];
                ldm4(tb, aKh + off);
                ldm4(tl, aKl + off);
                unsigned bh0[2] = {tb[0], tb[2]}, bh1[2] = {tb[1], tb[3]};
                unsigned bl0[2] = {tl[0], tl[2]}, bl1[2] = {tl[1], tl[3]};
                mma16816(s[kb * 2], ah, bh0);
                mma16816(s[kb * 2], ah, bl0);
                mma16816(s[kb * 2], al, bh0);
                mma16816(s[kb * 2 + 1], ah, bh1);
                mma16816(s[kb * 2 + 1], ah, bl1);
                mma16816(s[kb * 2 + 1], al, bh1);
            }
        }

        if (n0 + AN > m0) {
            int q0 = m0 + wm + (lane >> 2);
#pragma unroll
            for (int j = 0; j < 8; j++) {
                int k0 = n0 + j * 8 + (lane & 3) * 2;
                if (k0     > q0)     s[j][0] = -1e30f;
                if (k0 + 1 > q0)     s[j][1] = -1e30f;
                if (k0     > q0 + 8) s[j][2] = -1e30f;
                if (k0 + 1 > q0 + 8) s[j][3] = -1e30f;
            }
        }

        float mx0 = -1e30f, mx1 = -1e30f;
#pragma unroll
        for (int j = 0; j < 8; j++) {
            mx0 = fmaxf(mx0, fmaxf(s[j][0], s[j][1]));
            mx1 = fmaxf(mx1, fmaxf(s[j][2], s[j][3]));
        }
        mx0 = fmaxf(mx0, __shfl_xor_sync(0xffffffffu, mx0, 1));
        mx0 = fmaxf(mx0, __shfl_xor_sync(0xffffffffu, mx0, 2));
        mx1 = fmaxf(mx1, __shfl_xor_sync(0xffffffffu, mx1, 1));
        mx1 = fmaxf(mx1, __shfl_xor_sync(0xffffffffu, mx1, 2));
        float mn0 = fmaxf(m0r, mx0), mn1 = fmaxf(m1r, mx1);
        float f0 = exp2f((m0r - mn0) * L2E), f1 = exp2f((m1r - mn1) * L2E);
        m0r = mn0; m1r = mn1;

        unsigned ph[8], ph2[8], pl[8], pl2[8];
        float sum0 = 0.f, sum1 = 0.f;
#pragma unroll
        for (int j = 0; j < 8; j++) {
            float p0 = exp2f((s[j][0] - mn0) * L2E);
            float p1 = exp2f((s[j][1] - mn0) * L2E);
            float p2 = exp2f((s[j][2] - mn1) * L2E);
            float p3 = exp2f((s[j][3] - mn1) * L2E);
            sum0 += p0 + p1; sum1 += p2 + p3;
            bf16 a, b, c, d;
            split1(p0, a, c); split1(p1, b, d);
            ph[j] = packbf(a, b); pl[j] = packbf(c, d);
            split1(p2, a, c); split1(p3, b, d);
            ph2[j] = packbf(a, b); pl2[j] = packbf(c, d);
        }
        sum0 += __shfl_xor_sync(0xffffffffu, sum0, 1);
        sum0 += __shfl_xor_sync(0xffffffffu, sum0, 2);
        sum1 += __shfl_xor_sync(0xffffffffu, sum1, 1);
        sum1 += __shfl_xor_sync(0xffffffffu, sum1, 2);
        l0 = l0 * f0 + sum0;
        l1 = l1 * f1 + sum1;
#pragma unroll
        for (int j = 0; j < 16; j++) {
            o[j][0] *= f0; o[j][1] *= f0; o[j][2] *= f1; o[j][3] *= f1;
        }

#pragma unroll
        for (int kt = 0; kt < 4; kt++) {
            unsigned ahp[4] = {ph[2 * kt], ph2[2 * kt], ph[2 * kt + 1], ph2[2 * kt + 1]};
            unsigned alp[4] = {pl[2 * kt], pl2[2 * kt], pl[2 * kt + 1], pl2[2 * kt + 1]};
#pragma unroll
            for (int nv = 0; nv < 8; nv++) {
                int r = kt * 16 + (lane & 15), c = nv * 2 + (lane >> 4);
                int pc = c ^ (r & 7);
                unsigned off = (unsigned)(r * 256 + pc * 16);
                unsigned tb[4], tl[4];
                ldm4t(tb, aVh + off);
                ldm4t(tl, aVl + off);
                unsigned bh0[2] = {tb[0], tb[1]}, bh1[2] = {tb[2], tb[3]};
                unsigned bl0[2] = {tl[0], tl[1]}, bl1[2] = {tl[2], tl[3]};
                mma16816(o[nv * 2], ahp, bh0);
                mma16816(o[nv * 2], ahp, bl0);
                mma16816(o[nv * 2], alp, bh0);
                mma16816(o[nv * 2 + 1], ahp, bh1);
                mma16816(o[nv * 2 + 1], ahp, bl1);
                mma16816(o[nv * 2 + 1], alp, bh1);
            }
        }
    }

    float il0 = 1.f / l0, il1 = 1.f / l1;
    int r0 = m0 + wm + (lane >> 2);
#pragma unroll
    for (int j = 0; j < 16; j++) {
        int dv = j * 8 + (lane & 3) * 2;
        bf16 a, b, c, d;
        split1(o[j][0] * il0, a, c);
        split1(o[j][1] * il0, b, d);
        size_t off = (size_t)r0 * (NH * DV) + h * DV + dv;
        *(__nv_bfloat162*)(attn_h + off) = __nv_bfloat162(a, b);
        *(__nv_bfloat162*)(attn_l + off) = __nv_bfloat162(c, d);
        split1(o[j][2] * il1, a, c);
        split1(o[j][3] * il1, b, d);
        off += (size_t)8 * (NH * DV);
        *(__nv_bfloat162*)(attn_h + off) = __nv_bfloat162(a, b);
        *(__nv_bfloat162*)(attn_l + off) = __nv_bfloat162(c, d);
    }
}

// ---------------------------------------------------------------------------
// Launch
// ---------------------------------------------------------------------------
static inline void launch_split(const float* x, bf16* hi, bf16* lo, int n) {
    int n4 = n / 4;
    split_kernel<<<(n4 + 255) / 256, 256>>>(x, hi, lo, n4);
}

extern "C" void kernel_launch(void* const* d_in, const int* in_sizes, int n_in,
                              void* d_out, int out_size)
{
    const int*   positions = (const int*)  d_in[0];
    const float* hidden    = (const float*)d_in[1];
    const float* scaling   = (const float*)d_in[2];
    const float* w_q_a     = (const float*)d_in[3];
    const float* q_a_ln_w  = (const float*)d_in[4];
    const float* w_q_b     = (const float*)d_in[5];
    const float* w_kv_a    = (const float*)d_in[6];
    const float* kv_a_ln_w = (const float*)d_in[7];
    const float* w_kv_b    = (const float*)d_in[8];
    const float* w_o       = (const float*)d_in[9];
    const float* cs_cache  = (const float*)d_in[10];
    float* out = (float*)d_out;

    bf16 *Hh, *Hl, *Wa_h, *Wa_l, *Wqb_h, *Wqb_l;
    bf16 *Wkvb_h, *Wkvb_l, *Wo_h, *Wo_l, *qa_h, *qa_l, *kvan_h, *kvan_l;
    bf16 *qhp, *qlp, *khp, *klp, *vhp, *vlp, *attn_h, *attn_l;
    float *qalat, *qb, *kv;
    cudaGetSymbolAddress((void**)&Hh, g_Hh);       cudaGetSymbolAddress((void**)&Hl, g_Hl);
    cudaGetSymbolAddress((void**)&Wa_h, g_Wa_h);   cudaGetSymbolAddress((void**)&Wa_l, g_Wa_l);
    cudaGetSymbolAddress((void**)&Wqb_h, g_Wqb_h); cudaGetSymbolAddress((void**)&Wqb_l, g_Wqb_l);
    cudaGetSymbolAddress((void**)&Wkvb_h, g_Wkvb_h); cudaGetSymbolAddress((void**)&Wkvb_l, g_Wkvb_l);
    cudaGetSymbolAddress((void**)&Wo_h, g_Wo_h);   cudaGetSymbolAddress((void**)&Wo_l, g_Wo_l);
    cudaGetSymbolAddress((void**)&qa_h, g_qa_h);   cudaGetSymbolAddress((void**)&qa_l, g_qa_l);
    cudaGetSymbolAddress((void**)&kvan_h, g_kvan_h); cudaGetSymbolAddress((void**)&kvan_l, g_kvan_l);
    cudaGetSymbolAddress((void**)&qhp, g_qh); cudaGetSymbolAddress((void**)&qlp, g_ql);
    cudaGetSymbolAddress((void**)&khp, g_kh); cudaGetSymbolAddress((void**)&klp, g_kl);
    cudaGetSymbolAddress((void**)&vhp, g_vh); cudaGetSymbolAddress((void**)&vlp, g_vl);
    cudaGetSymbolAddress((void**)&attn_h, g_attn_h); cudaGetSymbolAddress((void**)&attn_l, g_attn_l);
    cudaGetSymbolAddress((void**)&qalat, g_qalat);
    cudaGetSymbolAddress((void**)&qb, g_q);
    cudaGetSymbolAddress((void**)&kv, g_kv);

    cudaFuncSetAttribute(mma_gemm_kernel, cudaFuncAttributeMaxDynamicSharedMemorySize,
                         GEMM_SMEM);
    cudaFuncSetAttribute(mma_gemm_dual_kernel, cudaFuncAttributeMaxDynamicSharedMemorySize,
                         GEMM_SMEM);
    cudaFuncSetAttribute(flash_mma_kernel, cudaFuncAttributeMaxDynamicSharedMemorySize,
                         FLASH_SMEM);

    // 1. split inputs + weights (w_q_a | w_kv_a fused into one [5120,2112])
    launch_split(hidden, Hh, Hl, T_TOK * HID);
    {
        int total4 = HID * FUSED_N / 4;
        split_fuse_kernel<<<(total4 + 255) / 256, 256>>>(w_q_a, w_kv_a, Wa_h, Wa_l);
    }
    launch_split(w_q_b, Wqb_h, Wqb_l, Q_RANK * NH * DQK);
    launch_split(w_kv_b, Wkvb_h, Wkvb_l, KV_RANK * NH * KV_OUT);
    launch_split(w_o, Wo_h, Wo_l, NH * DV * HID);

    const dim3 blk(256);
    const int MT = T_TOK / CBM;  // 24

    // 2. [qa | latent] = hidden @ [w_q_a | w_kv_a]   [3072,5120]x[5120,2112]
    mma_gemm_kernel<<<dim3((FUSED_N + CBN - 1) / CBN, MT), blk, GEMM_SMEM>>>(
        Hh, Hl, Wa_h, Wa_l, qalat, T_TOK, FUSED_N, HID);
    // 3. rmsnorm + split (qa: cols 0-1535; kv_a: cols 1536-2047 of fused rows)
    rmsnorm_split_kernel<<<T_TOK, 256>>>(qalat, q_a_ln_w, qa_h, qa_l, Q_RANK, FUSED_N);
    rmsnorm_split_kernel<<<T_TOK, 256>>>(qalat + Q_RANK, kv_a_ln_w, kvan_h, kvan_l,
                                         KV_RANK, FUSED_N);
    // 4+5 fused launch: q = qa_n @ w_q_b   AND   kv = kvan @ w_kv_b
    {
        const int nblk_q  = (NH * DQK) / CBN;    // 24
        const int nblk_kv = (NH * KV_OUT) / CBN; // 32
        mma_gemm_dual_kernel<<<dim3(nblk_q + nblk_kv, MT), blk, GEMM_SMEM>>>(
            qa_h, qa_l, Wqb_h, Wqb_l, qb, NH * DQK, Q_RANK, nblk_q,
            kvan_h, kvan_l, Wkvb_h, Wkvb_l, kv, NH * KV_OUT, KV_RANK);
    }
    // 6. rope + scale folding + head-major splits (latent = fused cols 1536+)
    prep_kernel<<<T_TOK, 256>>>(positions, cs_cache, scaling,
                                qalat + Q_RANK, FUSED_N, qb, kv,
                                qhp, qlp, khp, klp, vhp, vlp);
    // 7. tensor-core flash attention (heavy-first ordering)
    flash_mma_kernel<<<dim3(T_TOK / AM, NH), 256, FLASH_SMEM>>>(
        qhp, qlp, khp, klp, vhp, vlp, attn_h, attn_l);
    // 8. out = attn @ w_o   [3072,2048]x[2048,5120]
    mma_gemm_kernel<<<dim3(HID / CBN, MT), blk, GEMM_SMEM>>>(
        attn_h, attn_l, Wo_h, Wo_l, out, T_TOK, HID, NH * DV);
}

// round 9
// speedup vs baseline: 1.3676x; 1.3663x over previous
#include <cuda_runtime.h>
#include <cuda_fp16.h>
#include <math.h>

// Problem constants
#define T_TOK 3072
#define HID 5120
#define NH 16
#define DN 128
#define DR 64
#define DQK 192       // DN + DR
#define DV 128
#define Q_RANK 1536
#define KV_RANK 512
#define KV_A_OUT (KV_RANK + DR)   // 576
#define KV_OUT (DN + DV)          // 256
#define FUSED_N (Q_RANK + KV_A_OUT)   // 2112

typedef __half hf;

// ---------------------------------------------------------------------------
// Scratch (allocation-free: __device__ globals)
// A-side operands: fp16 hi+lo (exact to 2^-22). B-side operands: fp16 hi only.
// ---------------------------------------------------------------------------
__device__ hf g_Hh[T_TOK * HID], g_Hl[T_TOK * HID];
__device__ hf g_Wa_h[HID * FUSED_N];                 // fused [5120,2112] hi
__device__ hf g_Wqb_h[Q_RANK * NH * DQK];
__device__ hf g_Wkvb_h[KV_RANK * NH * KV_OUT];
__device__ hf g_Wo_h[NH * DV * HID];
__device__ float g_qalat[T_TOK * FUSED_N];           // fused qa | latent (fp32)
__device__ hf g_qa_h[T_TOK * Q_RANK], g_qa_l[T_TOK * Q_RANK];
__device__ hf g_kvan_h[T_TOK * KV_RANK], g_kvan_l[T_TOK * KV_RANK];
__device__ float g_q[T_TOK * NH * DQK];
__device__ float g_kv[T_TOK * NH * KV_OUT];
// head-major tensors for flash: Q hi/lo, K hi, V hi
__device__ hf g_qh[NH * T_TOK * DQK], g_ql[NH * T_TOK * DQK];
__device__ hf g_kh[NH * T_TOK * DQK];
__device__ hf g_vh[NH * T_TOK * DV];
__device__ hf g_attn_h[T_TOK * NH * DV], g_attn_l[T_TOK * NH * DV];

// ---------------------------------------------------------------------------
// PTX helpers
// ---------------------------------------------------------------------------
__device__ __forceinline__ unsigned smem_u32(const void* p) {
    return (unsigned)__cvta_generic_to_shared(p);
}
__device__ __forceinline__ void cp16(unsigned s, const void* g, int srcsz) {
    asm volatile("cp.async.cg.shared.global [%0], [%1], 16, %2;\n"
                 :: "r"(s), "l"(g), "r"(srcsz));
}
__device__ __forceinline__ void cp_commit() {
    asm volatile("cp.async.commit_group;\n" ::);
}
template<int N> __device__ __forceinline__ void cp_wait() {
    asm volatile("cp.async.wait_group %0;\n" :: "n"(N));
}
__device__ __forceinline__ void ldm4(unsigned* d, unsigned a) {
    asm volatile("ldmatrix.sync.aligned.m8n8.x4.shared.b16 {%0,%1,%2,%3}, [%4];\n"
                 : "=r"(d[0]), "=r"(d[1]), "=r"(d[2]), "=r"(d[3]) : "r"(a));
}
__device__ __forceinline__ void ldm4t(unsigned* d, unsigned a) {
    asm volatile("ldmatrix.sync.aligned.m8n8.x4.trans.shared.b16 {%0,%1,%2,%3}, [%4];\n"
                 : "=r"(d[0]), "=r"(d[1]), "=r"(d[2]), "=r"(d[3]) : "r"(a));
}
__device__ __forceinline__ void mma16816(float* c, const unsigned* a, const unsigned* b) {
    asm volatile(
        "mma.sync.aligned.m16n8k16.row.col.f32.f16.f16.f32 "
        "{%0,%1,%2,%3}, {%4,%5,%6,%7}, {%8,%9}, {%0,%1,%2,%3};\n"
        : "+f"(c[0]), "+f"(c[1]), "+f"(c[2]), "+f"(c[3])
        : "r"(a[0]), "r"(a[1]), "r"(a[2]), "r"(a[3]), "r"(b[0]), "r"(b[1]));
}
__device__ __forceinline__ void split1(float x, hf& h, hf& l) {
    h = __float2half_rn(x);
    l = __float2half_rn(x - __half2float(h));
}
__device__ __forceinline__ unsigned packhf(hf a, hf b) {
    __half2 t(a, b);
    return *(unsigned*)&t;
}

// ---------------------------------------------------------------------------
// Split-convert: fp32 -> (hi, lo) fp16. n multiple of 4.
// ---------------------------------------------------------------------------
__global__ void split_kernel(const float* __restrict__ x,
                             hf* __restrict__ hi, hf* __restrict__ lo, int n4)
{
    int i = blockIdx.x * blockDim.x + threadIdx.x;
    if (i >= n4) return;
    float4 v = ((const float4*)x)[i];
    hf h0, h1, h2, h3, l0, l1, l2, l3;
    split1(v.x, h0, l0); split1(v.y, h1, l1); split1(v.z, h2, l2); split1(v.w, h3, l3);
    __half2* H = (__half2*)hi;
    __half2* L = (__half2*)lo;
    H[i * 2]     = __half2(h0, h1);
    H[i * 2 + 1] = __half2(h2, h3);
    L[i * 2]     = __half2(l0, l1);
    L[i * 2 + 1] = __half2(l2, l3);
}

// fp32 -> fp16 hi only (for B-side weights)
__global__ void split_h_kernel(const float* __restrict__ x,
                               hf* __restrict__ hi, int n4)
{
    int i = blockIdx.x * blockDim.x + threadIdx.x;
    if (i >= n4) return;
    float4 v = ((const float4*)x)[i];
    __half2* H = (__half2*)hi;
    H[i * 2]     = __half2(__float2half_rn(v.x), __float2half_rn(v.y));
    H[i * 2 + 1] = __half2(__float2half_rn(v.z), __float2half_rn(v.w));
}

// Fused-weight hi split: w_q_a [5120,1536] | w_kv_a [5120,576] -> [5120,2112]
__global__ void split_fuse_kernel(const float* __restrict__ wqa,
                                  const float* __restrict__ wkva,
                                  hf* __restrict__ hi)
{
    int i = blockIdx.x * blockDim.x + threadIdx.x;
    int total4 = HID * FUSED_N / 4;
    if (i >= total4) return;
    int e0 = i * 4;
    int k = e0 / FUSED_N, n = e0 % FUSED_N;
    float v[4];
    if (n + 3 < Q_RANK) {
        const float* src = wqa + (size_t)k * Q_RANK + n;
        v[0] = src[0]; v[1] = src[1]; v[2] = src[2]; v[3] = src[3];
    } else if (n >= Q_RANK) {
        const float* src = wkva + (size_t)k * KV_A_OUT + (n - Q_RANK);
        v[0] = src[0]; v[1] = src[1]; v[2] = src[2]; v[3] = src[3];
    } else {
#pragma unroll
        for (int j = 0; j < 4; j++) {
            int nn = n + j;
            v[j] = (nn < Q_RANK) ? wqa[(size_t)k * Q_RANK + nn]
                                 : wkva[(size_t)k * KV_A_OUT + (nn - Q_RANK)];
        }
    }
    hf h[4];
#pragma unroll
    for (int j = 0; j < 4; j++) h[j] = __float2half_rn(v[j]);
    *(uint2*)(hi + e0) = *(uint2*)h;
}

// ---------------------------------------------------------------------------
// fp16 2-term tensor-core GEMM:  C = (Ah+Al) @ Bh  (error ~2^-12 from B lo).
// CTA 128x128, BK=32, 256 threads (8 warps, warp tile 64x32), 3-stage
// cp.async pipeline (24KB/stage, 72KB total), XOR-swizzled smem + ldmatrix.
// ---------------------------------------------------------------------------
#define CBM 128
#define CBN 128
#define CBK 32
#define A_TILE_B 8192
#define B_TILE_B 8192
#define STAGE_B  (2 * A_TILE_B + B_TILE_B)   // 24576
#define NSTAGE 3
#define GEMM_SMEM (NSTAGE * STAGE_B)         // 73728

__device__ __forceinline__ void gemm_cta(
    char* smem, int tid,
    const hf* __restrict__ Ah, const hf* __restrict__ Al,
    const hf* __restrict__ Bh,
    float* __restrict__ C, int m0, int n0, int N, int K)
{
    const int lane = tid & 31;
    const int warp = tid >> 5;
    const int wm0 = (warp >> 2) * 64;
    const int wn0 = (warp & 3) * 32;

    float acc[16][4];
#pragma unroll
    for (int i = 0; i < 16; i++)
#pragma unroll
        for (int j = 0; j < 4; j++) acc[i][j] = 0.f;

    auto load_stage = [&](int k0, int s) {
        char* base = smem + s * STAGE_B;
        // A: 128 rows x 4 16B-chunks (64B rows) = 512 chunks/tile; 2/thread
#pragma unroll
        for (int i = 0; i < 2; i++) {
            int ch = tid + i * 256;
            int r = ch >> 2, c = ch & 3;
            int pc = c ^ ((r >> 1) & 3);
            size_t goff = (size_t)(m0 + r) * K + k0 + c * 8;
            cp16(smem_u32(base + r * 64 + pc * 16), Ah + goff, 16);
            cp16(smem_u32(base + A_TILE_B + r * 64 + pc * 16), Al + goff, 16);
        }
        // B: 32 rows x 16 chunks (256B rows) = 512 chunks; 2/thread
#pragma unroll
        for (int i = 0; i < 2; i++) {
            int ch = tid + i * 256;
            int r = ch >> 4, c = ch & 15;
            int pc = c ^ (r & 7);
            int gn = n0 + c * 8;
            int sz = (gn < N) ? 16 : 0;
            size_t goff = (size_t)(k0 + r) * N + (gn < N ? gn : 0);
            cp16(smem_u32(base + 2 * A_TILE_B + r * 256 + pc * 16), Bh + goff, sz);
        }
    };

    auto compute_stage = [&](int s) {
        char* base = smem + s * STAGE_B;
        unsigned aH = smem_u32(base);
        unsigned aL = aH + A_TILE_B;
        unsigned bH = aH + 2 * A_TILE_B;
#pragma unroll
        for (int kk = 0; kk < 2; kk++) {
            unsigned ah[4][4], al[4][4], bh[4][2];
            const int r_lo = lane & 15;
            const int cch = kk * 2 + (lane >> 4);
#pragma unroll
            for (int mi = 0; mi < 4; mi++) {
                int r = wm0 + mi * 16 + r_lo;
                int pc = cch ^ ((r >> 1) & 3);
                unsigned off = (unsigned)(r * 64 + pc * 16);
                ldm4(ah[mi], aH + off);
                ldm4(al[mi], aL + off);
            }
            {
                int r = kk * 16 + (lane & 15);
#pragma unroll
                for (int ni = 0; ni < 2; ni++) {
                    int cc = ((wn0 + ni * 16) >> 3) + ((lane >> 4) & 1);
                    int pc = cc ^ (r & 7);
                    unsigned off = (unsigned)(r * 256 + pc * 16);
                    unsigned t[4];
                    ldm4t(t, bH + off);
                    bh[ni * 2][0] = t[0]; bh[ni * 2][1] = t[1];
                    bh[ni * 2 + 1][0] = t[2]; bh[ni * 2 + 1][1] = t[3];
                }
            }
#pragma unroll
            for (int mi = 0; mi < 4; mi++)
#pragma unroll
                for (int nj = 0; nj < 4; nj++) {
                    mma16816(acc[mi * 4 + nj], ah[mi], bh[nj]);
                    mma16816(acc[mi * 4 + nj], al[mi], bh[nj]);
                }
        }
    };

    const int KT = K / CBK;
    load_stage(0, 0); cp_commit();
    load_stage(CBK, 1); cp_commit();
    for (int kt = 0; kt < KT; kt++) {
        cp_wait<1>();
        __syncthreads();
        if (kt + 2 < KT) load_stage((kt + 2) * CBK, (kt + 2) % NSTAGE);
        cp_commit();
        compute_stage(kt % NSTAGE);
    }

#pragma unroll
    for (int mi = 0; mi < 4; mi++) {
        int row = m0 + wm0 + mi * 16 + (lane >> 2);
#pragma unroll
        for (int nj = 0; nj < 4; nj++) {
            int col = n0 + wn0 + nj * 8 + (lane & 3) * 2;
            if (col < N) {
                float* a = acc[mi * 4 + nj];
                *(float2*)(C + (size_t)row * N + col)       = make_float2(a[0], a[1]);
                *(float2*)(C + (size_t)(row + 8) * N + col) = make_float2(a[2], a[3]);
            }
        }
    }
}

__global__ __launch_bounds__(256) void mma_gemm_kernel(
    const hf* __restrict__ Ah, const hf* __restrict__ Al,
    const hf* __restrict__ Bh,
    float* __restrict__ C, int M, int N, int K)
{
    extern __shared__ char smem[];
    gemm_cta(smem, threadIdx.x, Ah, Al, Bh, C,
             blockIdx.y * CBM, blockIdx.x * CBN, N, K);
}

// Dual GEMM: first nblk1 n-tiles run problem 1, rest run problem 2.
__global__ __launch_bounds__(256) void mma_gemm_dual_kernel(
    const hf* __restrict__ Ah1, const hf* __restrict__ Al1,
    const hf* __restrict__ Bh1,
    float* __restrict__ C1, int N1, int K1, int nblk1,
    const hf* __restrict__ Ah2, const hf* __restrict__ Al2,
    const hf* __restrict__ Bh2,
    float* __restrict__ C2, int N2, int K2)
{
    extern __shared__ char smem[];
    const int m0 = blockIdx.y * CBM;
    if ((int)blockIdx.x < nblk1) {
        gemm_cta(smem, threadIdx.x, Ah1, Al1, Bh1, C1,
                 m0, blockIdx.x * CBN, N1, K1);
    } else {
        gemm_cta(smem, threadIdx.x, Ah2, Al2, Bh2, C2,
                 m0, (blockIdx.x - nblk1) * CBN, N2, K2);
    }
}

// ---------------------------------------------------------------------------
// RMSNorm + split (input row stride decoupled from width)
// ---------------------------------------------------------------------------
__global__ void rmsnorm_split_kernel(const float* __restrict__ in,
                                     const float* __restrict__ w,
                                     hf* __restrict__ ohi, hf* __restrict__ olo,
                                     int W, int in_stride)
{
    const int t = blockIdx.x;
    const float* row = in + (size_t)t * in_stride;

    float ss = 0.f;
    for (int i = threadIdx.x; i < W; i += blockDim.x) {
        float v = row[i];
        ss += v * v;
    }
    __shared__ float red[32];
#pragma unroll
    for (int o = 16; o; o >>= 1) ss += __shfl_xor_sync(0xffffffffu, ss, o);
    if ((threadIdx.x & 31) == 0) red[threadIdx.x >> 5] = ss;
    __syncthreads();
    if (threadIdx.x < 32) {
        float v = (threadIdx.x < (blockDim.x >> 5)) ? red[threadIdx.x] : 0.f;
#pragma unroll
        for (int o = 16; o; o >>= 1) v += __shfl_xor_sync(0xffffffffu, v, o);
        if (threadIdx.x == 0) red[0] = v;
    }
    __syncthreads();
    const float inv = rsqrtf(red[0] / (float)W + 1e-6f);
    for (int i = threadIdx.x; i < W; i += blockDim.x) {
        float y = row[i] * inv * w[i];
        hf h, l;
        split1(y, h, l);
        ohi[(size_t)t * W + i] = h;
        olo[(size_t)t * W + i] = l;
    }
}

// ---------------------------------------------------------------------------
// Prep: RoPE q_pe (in place) + k_pe, fold (scaling * 1/sqrt(192)) into q,
// emit head-major Q hi/lo, K hi, V hi (fp16).
// ---------------------------------------------------------------------------
__global__ void prep_kernel(const int* __restrict__ positions,
                            const float* __restrict__ cs_cache,
                            const float* __restrict__ scaling,
                            const float* __restrict__ latent, int lat_stride,
                            float* __restrict__ qb,          // [T,16,192] in/out
                            const float* __restrict__ kvb,   // [T,16,256]
                            hf* __restrict__ qh, hf* __restrict__ ql,
                            hf* __restrict__ kh, hf* __restrict__ vh)
{
    __shared__ float kpe_s[DR];
    const int t = blockIdx.x;
    const int pos = positions[t];
    const float* cs = cs_cache + (size_t)pos * DR;
    const float qsc = scaling[t] * 0.07216878364870322f;  // llama4 * 1/sqrt(192)
    float* qrow = qb + (size_t)t * (NH * DQK);

    for (int idx = threadIdx.x; idx < NH * 32; idx += blockDim.x) {
        int hh = idx >> 5, i = idx & 31;
        float c = cs[i], s = cs[32 + i];
        float x1 = qrow[hh * DQK + DN + i];
        float x2 = qrow[hh * DQK + DN + 32 + i];
        qrow[hh * DQK + DN + i]      = x1 * c - x2 * s;
        qrow[hh * DQK + DN + 32 + i] = x2 * c + x1 * s;
    }
    if (threadIdx.x < 32) {
        int i = threadIdx.x;
        float c = cs[i], s = cs[32 + i];
        float x1 = latent[(size_t)t * lat_stride + KV_RANK + i];
        float x2 = latent[(size_t)t * lat_stride + KV_RANK + 32 + i];
        kpe_s[i]      = x1 * c - x2 * s;
        kpe_s[32 + i] = x2 * c + x1 * s;
    }
    __syncthreads();
    for (int idx = threadIdx.x; idx < NH * DQK; idx += blockDim.x) {
        int hh = idx / DQK, d = idx % DQK;
        size_t o = ((size_t)hh * T_TOK + t) * DQK + d;
        hf hi, lo;
        split1(qrow[idx] * qsc, hi, lo);
        qh[o] = hi; ql[o] = lo;
        float kvv = (d < DN) ? kvb[(size_t)t * (NH * KV_OUT) + hh * KV_OUT + d]
                             : kpe_s[d - DN];
        kh[o] = __float2half_rn(kvv);
    }
    for (int idx = threadIdx.x; idx < NH * DV; idx += blockDim.x) {
        int hh = idx / DV, d = idx % DV;
        size_t o = ((size_t)hh * T_TOK + t) * DV + d;
        vh[o] = __float2half_rn(kvb[(size_t)t * (NH * KV_OUT) + hh * KV_OUT + DN + d]);
    }
}

// ---------------------------------------------------------------------------
// Tensor-core flash attention (fp16 2-term, causal).
// Q exact (hi+lo), K hi, V hi; P exact (hi+lo).
// ---------------------------------------------------------------------------
#define AM 128
#define AN 64
#define FQH 0
#define FQL (FQH + AM*384)
#define FKH (FQL + AM*384)
#define FVH (FKH + AN*384)
#define FLASH_SMEM (FVH + AN*256)    // 139264 B

__global__ __launch_bounds__(256) void flash_mma_kernel(
    const hf* __restrict__ qh, const hf* __restrict__ ql,
    const hf* __restrict__ kh, const hf* __restrict__ vh,
    hf* __restrict__ attn_h, hf* __restrict__ attn_l)
{
    extern __shared__ char smem[];
    const int m0 = blockIdx.x * AM;
    const int h  = blockIdx.y;
    const int tid = threadIdx.x, lane = tid & 31, warp = tid >> 5;
    const int wm = warp * 16;
    const float L2E = 1.4426950408889634f;

    {
        const hf* qh_g = qh + ((size_t)h * T_TOK + m0) * DQK;
        const hf* ql_g = ql + ((size_t)h * T_TOK + m0) * DQK;
        for (int i = tid; i < AM * 24; i += 256) {
            int r = i / 24, c = i % 24, pc = c ^ (r & 7);
            cp16(smem_u32(smem + FQH + r * 384 + pc * 16), qh_g + (size_t)r * DQK + c * 8, 16);
            cp16(smem_u32(smem + FQL + r * 384 + pc * 16), ql_g + (size_t)r * DQK + c * 8, 16);
        }
        cp_commit();
    }

    float o[16][4];
#pragma unroll
    for (int i = 0; i < 16; i++)
#pragma unroll
        for (int j = 0; j < 4; j++) o[i][j] = 0.f;
    float m0r = -1e30f, m1r = -1e30f, l0 = 0.f, l1 = 0.f;

    const unsigned aQh = smem_u32(smem + FQH), aQl = smem_u32(smem + FQL);
    const unsigned aKh = smem_u32(smem + FKH);
    const unsigned aVh = smem_u32(smem + FVH);

    const int ntiles = 2 * blockIdx.x + 2;
    for (int nt = 0; nt < ntiles; nt++) {
        const int n0 = nt * AN;
        __syncthreads();
        {
            const hf* kh_g = kh + ((size_t)h * T_TOK + n0) * DQK;
            for (int i = tid; i < AN * 24; i += 256) {
                int r = i / 24, c = i % 24, pc = c ^ (r & 7);
                cp16(smem_u32(smem + FKH + r * 384 + pc * 16), kh_g + (size_t)r * DQK + c * 8, 16);
            }
            const hf* vh_g = vh + ((size_t)h * T_TOK + n0) * DV;
            for (int i = tid; i < AN * 16; i += 256) {
                int r = i >> 4, c = i & 15, pc = c ^ (r & 7);
                cp16(smem_u32(smem + FVH + r * 256 + pc * 16), vh_g + (size_t)r * DV + c * 8, 16);
            }
        }
        cp_commit();
        cp_wait<0>();
        __syncthreads();

        float s[8][4];
#pragma unroll
        for (int j = 0; j < 8; j++)
#pragma unroll
            for (int c = 0; c < 4; c++) s[j][c] = 0.f;

#pragma unroll
        for (int kt = 0; kt < 12; kt++) {
            unsigned ah[4], al[4];
            {
                int r = wm + (lane & 15), c = kt * 2 + (lane >> 4);
                int pc = c ^ (r & 7);
                unsigned off = (unsigned)(r * 384 + pc * 16);
                ldm4(ah, aQh + off);
                ldm4(al, aQl + off);
            }
#pragma unroll
            for (int kb = 0; kb < 4; kb++) {
                int r = kb * 16 + (lane & 15), c = kt * 2 + (lane >> 4);
                int pc = c ^ (r & 7);
                unsigned off = (unsigned)(r * 384 + pc * 16);
                unsigned tb[4];
                ldm4(tb, aKh + off);
                unsigned bh0[2] = {tb[0], tb[2]}, bh1[2] = {tb[1], tb[3]};
                mma16816(s[kb * 2], ah, bh0);
                mma16816(s[kb * 2], al, bh0);
                mma16816(s[kb * 2 + 1], ah, bh1);
                mma16816(s[kb * 2 + 1], al, bh1);
            }
        }

        if (n0 + AN > m0) {
            int q0 = m0 + wm + (lane >> 2);
#pragma unroll
            for (int j = 0; j < 8; j++) {
                int k0 = n0 + j * 8 + (lane & 3) * 2;
                if (k0     > q0)     s[j][0] = -1e30f;
                if (k0 + 1 > q0)     s[j][1] = -1e30f;
                if (k0     > q0 + 8) s[j][2] = -1e30f;
                if (k0 + 1 > q0 + 8) s[j][3] = -1e30f;
            }
        }

        float mx0 = -1e30f, mx1 = -1e30f;
#pragma unroll
        for (int j = 0; j < 8; j++) {
            mx0 = fmaxf(mx0, fmaxf(s[j][0], s[j][1]));
            mx1 = fmaxf(mx1, fmaxf(s[j][2], s[j][3]));
        }
        mx0 = fmaxf(mx0, __shfl_xor_sync(0xffffffffu, mx0, 1));
        mx0 = fmaxf(mx0, __shfl_xor_sync(0xffffffffu, mx0, 2));
        mx1 = fmaxf(mx1, __shfl_xor_sync(0xffffffffu, mx1, 1));
        mx1 = fmaxf(mx1, __shfl_xor_sync(0xffffffffu, mx1, 2));
        float mn0 = fmaxf(m0r, mx0), mn1 = fmaxf(m1r, mx1);
        float f0 = exp2f((m0r - mn0) * L2E), f1 = exp2f((m1r - mn1) * L2E);
        m0r = mn0; m1r = mn1;

        unsigned ph[8], ph2[8], pl[8], pl2[8];
        float sum0 = 0.f, sum1 = 0.f;
#pragma unroll
        for (int j = 0; j < 8; j++) {
            float p0 = exp2f((s[j][0] - mn0) * L2E);
            float p1 = exp2f((s[j][1] - mn0) * L2E);
            float p2 = exp2f((s[j][2] - mn1) * L2E);
            float p3 = exp2f((s[j][3] - mn1) * L2E);
            sum0 += p0 + p1; sum1 += p2 + p3;
            hf a, b, c, d;
            split1(p0, a, c); split1(p1, b, d);
            ph[j] = packhf(a, b); pl[j] = packhf(c, d);
            split1(p2, a, c); split1(p3, b, d);
            ph2[j] = packhf(a, b); pl2[j] = packhf(c, d);
        }
        sum0 += __shfl_xor_sync(0xffffffffu, sum0, 1);
        sum0 += __shfl_xor_sync(0xffffffffu, sum0, 2);
        sum1 += __shfl_xor_sync(0xffffffffu, sum1, 1);
        sum1 += __shfl_xor_sync(0xffffffffu, sum1, 2);
        l0 = l0 * f0 + sum0;
        l1 = l1 * f1 + sum1;
#pragma unroll
        for (int j = 0; j < 16; j++) {
            o[j][0] *= f0; o[j][1] *= f0; o[j][2] *= f1; o[j][3] *= f1;
        }

#pragma unroll
        for (int kt = 0; kt < 4; kt++) {
            unsigned ahp[4] = {ph[2 * kt], ph2[2 * kt], ph[2 * kt + 1], ph2[2 * kt + 1]};
            unsigned alp[4] = {pl[2 * kt], pl2[2 * kt], pl[2 * kt + 1], pl2[2 * kt + 1]};
#pragma unroll
            for (int nv = 0; nv < 8; nv++) {
                int r = kt * 16 + (lane & 15), c = nv * 2 + (lane >> 4);
                int pc = c ^ (r & 7);
                unsigned off = (unsigned)(r * 256 + pc * 16);
                unsigned tb[4];
                ldm4t(tb, aVh + off);
                unsigned bh0[2] = {tb[0], tb[1]}, bh1[2] = {tb[2], tb[3]};
                mma16816(o[nv * 2], ahp, bh0);
                mma16816(o[nv * 2], alp, bh0);
                mma16816(o[nv * 2 + 1], ahp, bh1);
                mma16816(o[nv * 2 + 1], alp, bh1);
            }
        }
    }

    float il0 = 1.f / l0, il1 = 1.f / l1;
    int r0 = m0 + wm + (lane >> 2);
#pragma unroll
    for (int j = 0; j < 16; j++) {
        int dv = j * 8 + (lane & 3) * 2;
        hf a, b, c, d;
        split1(o[j][0] * il0, a, c);
        split1(o[j][1] * il0, b, d);
        size_t off = (size_t)r0 * (NH * DV) + h * DV + dv;
        *(__half2*)(attn_h + off) = __half2(a, b);
        *(__half2*)(attn_l + off) = __half2(c, d);
        split1(o[j][2] * il1, a, c);
        split1(o[j][3] * il1, b, d);
        off += (size_t)8 * (NH * DV);
        *(__half2*)(attn_h + off) = __half2(a, b);
        *(__half2*)(attn_l + off) = __half2(c, d);
    }
}

// ---------------------------------------------------------------------------
// Launch
// ---------------------------------------------------------------------------
static inline void launch_split(const float* x, hf* hi, hf* lo, int n) {
    int n4 = n / 4;
    split_kernel<<<(n4 + 255) / 256, 256>>>(x, hi, lo, n4);
}
static inline void launch_split_h(const float* x, hf* hi, int n) {
    int n4 = n / 4;
    split_h_kernel<<<(n4 + 255) / 256, 256>>>(x, hi, n4);
}

extern "C" void kernel_launch(void* const* d_in, const int* in_sizes, int n_in,
                              void* d_out, int out_size)
{
    const int*   positions = (const int*)  d_in[0];
    const float* hidden    = (const float*)d_in[1];
    const float* scaling   = (const float*)d_in[2];
    const float* w_q_a     = (const float*)d_in[3];
    const float* q_a_ln_w  = (const float*)d_in[4];
    const float* w_q_b     = (const float*)d_in[5];
    const float* w_kv_a    = (const float*)d_in[6];
    const float* kv_a_ln_w = (const float*)d_in[7];
    const float* w_kv_b    = (const float*)d_in[8];
    const float* w_o       = (const float*)d_in[9];
    const float* cs_cache  = (const float*)d_in[10];
    float* out = (float*)d_out;

    hf *Hh, *Hl, *Wa_h, *Wqb_h, *Wkvb_h, *Wo_h;
    hf *qa_h, *qa_l, *kvan_h, *kvan_l;
    hf *qhp, *qlp, *khp, *vhp, *attn_h, *attn_l;
    float *qalat, *qb, *kv;
    cudaGetSymbolAddress((void**)&Hh, g_Hh);       cudaGetSymbolAddress((void**)&Hl, g_Hl);
    cudaGetSymbolAddress((void**)&Wa_h, g_Wa_h);
    cudaGetSymbolAddress((void**)&Wqb_h, g_Wqb_h);
    cudaGetSymbolAddress((void**)&Wkvb_h, g_Wkvb_h);
    cudaGetSymbolAddress((void**)&Wo_h, g_Wo_h);
    cudaGetSymbolAddress((void**)&qa_h, g_qa_h);   cudaGetSymbolAddress((void**)&qa_l, g_qa_l);
    cudaGetSymbolAddress((void**)&kvan_h, g_kvan_h); cudaGetSymbolAddress((void**)&kvan_l, g_kvan_l);
    cudaGetSymbolAddress((void**)&qhp, g_qh); cudaGetSymbolAddress((void**)&qlp, g_ql);
    cudaGetSymbolAddress((void**)&khp, g_kh);
    cudaGetSymbolAddress((void**)&vhp, g_vh);
    cudaGetSymbolAddress((void**)&attn_h, g_attn_h); cudaGetSymbolAddress((void**)&attn_l, g_attn_l);
    cudaGetSymbolAddress((void**)&qalat, g_qalat);
    cudaGetSymbolAddress((void**)&qb, g_q);
    cudaGetSymbolAddress((void**)&kv, g_kv);

    cudaFuncSetAttribute(mma_gemm_kernel, cudaFuncAttributeMaxDynamicSharedMemorySize,
                         GEMM_SMEM);
    cudaFuncSetAttribute(mma_gemm_dual_kernel, cudaFuncAttributeMaxDynamicSharedMemorySize,
                         GEMM_SMEM);
    cudaFuncSetAttribute(flash_mma_kernel, cudaFuncAttributeMaxDynamicSharedMemorySize,
                         FLASH_SMEM);

    // 1. splits: hidden hi/lo; weights hi only (fused w_q_a|w_kv_a)
    launch_split(hidden, Hh, Hl, T_TOK * HID);
    {
        int total4 = HID * FUSED_N / 4;
        split_fuse_kernel<<<(total4 + 255) / 256, 256>>>(w_q_a, w_kv_a, Wa_h);
    }
    launch_split_h(w_q_b, Wqb_h, Q_RANK * NH * DQK);
    launch_split_h(w_kv_b, Wkvb_h, KV_RANK * NH * KV_OUT);
    launch_split_h(w_o, Wo_h, NH * DV * HID);

    const dim3 blk(256);
    const int MT = T_TOK / CBM;  // 24

    // 2. [qa | latent] = hidden @ [w_q_a | w_kv_a]
    mma_gemm_kernel<<<dim3((FUSED_N + CBN - 1) / CBN, MT), blk, GEMM_SMEM>>>(
        Hh, Hl, Wa_h, qalat, T_TOK, FUSED_N, HID);
    // 3. rmsnorm + split
    rmsnorm_split_kernel<<<T_TOK, 256>>>(qalat, q_a_ln_w, qa_h, qa_l, Q_RANK, FUSED_N);
    rmsnorm_split_kernel<<<T_TOK, 256>>>(qalat + Q_RANK, kv_a_ln_w, kvan_h, kvan_l,
                                         KV_RANK, FUSED_N);
    // 4+5 fused: q = qa_n @ w_q_b  AND  kv = kvan @ w_kv_b
    {
        const int nblk_q  = (NH * DQK) / CBN;    // 24
        const int nblk_kv = (NH * KV_OUT) / CBN; // 32
        mma_gemm_dual_kernel<<<dim3(nblk_q + nblk_kv, MT), blk, GEMM_SMEM>>>(
            qa_h, qa_l, Wqb_h, qb, NH * DQK, Q_RANK, nblk_q,
            kvan_h, kvan_l, Wkvb_h, kv, NH * KV_OUT, KV_RANK);
    }
    // 6. rope + scale + head-major fp16 tensors
    prep_kernel<<<T_TOK, 256>>>(positions, cs_cache, scaling,
                                qalat + Q_RANK, FUSED_N, qb, kv,
                                qhp, qlp, khp, vhp);
    // 7. flash attention
    flash_mma_kernel<<<dim3(T_TOK / AM, NH), 256, FLASH_SMEM>>>(
        qhp, qlp, khp, vhp, attn_h, attn_l);
    // 8. out = attn @ w_o
    mma_gemm_kernel<<<dim3(HID / CBN, MT), blk, GEMM_SMEM>>>(
        attn_h, attn_l, Wo_h, out, T_TOK, HID, NH * DV);
}